// round 1
// baseline (speedup 1.0000x reference)
#include <cuda_runtime.h>

#define Bb 4
#define Tt 4096
#define Cc 1024
#define Hh 64

// combined scale: softmax(QK^T * h^-0.5 * h^-0.5) = softmax(QK^T / 64)
// exp(x/64) = exp2(x * log2(e)/64)
#define S2L2E 0.022542110f

// scratch for projected Q/K/V  (static __device__ globals: allocation-free)
__device__ float g_Q[Bb * Tt * Hh];
__device__ float g_K[Bb * Tt * Hh];
__device__ float g_V[Bb * Tt * Hh];

// ---------------------------------------------------------------------------
// Projection: out[row][h] = sum_c x[row][c] * W[h][c]
// grid: (256 row-tiles, 1, 3 matrices), 128 threads.
// Thread tile: 4 rows (a*16+ty) x 8 cols (b*8+tx); strided row mapping keeps
// float4 smem reads conflict-free (consecutive rows within each instruction).
// ---------------------------------------------------------------------------
__global__ __launch_bounds__(128) void proj_kernel(
    const float* __restrict__ xq, const float* __restrict__ xk,
    const float* __restrict__ xv,
    const float* __restrict__ Wq, const float* __restrict__ Wk,
    const float* __restrict__ Wv)
{
    __shared__ float Xs[64][68];
    __shared__ float Ws[64][68];

    const float* x;
    const float* W;
    float* out;
    if (blockIdx.z == 0)      { x = xq; W = Wq; out = g_Q; }
    else if (blockIdx.z == 1) { x = xk; W = Wk; out = g_K; }
    else                      { x = xv; W = Wv; out = g_V; }

    const int tid = threadIdx.x;
    const int tx = tid & 7;     // 0..7  -> col groups
    const int ty = tid >> 3;    // 0..15 -> row groups
    const long row0 = (long)blockIdx.x * 64;

    float acc[4][8];
#pragma unroll
    for (int a = 0; a < 4; a++)
#pragma unroll
        for (int b = 0; b < 8; b++) acc[a][b] = 0.f;

    for (int k0 = 0; k0 < Cc; k0 += 64) {
        // cooperative loads: 64 rows x 64 k, float4, fully coalesced
        for (int i = tid; i < 64 * 16; i += 128) {
            int r = i >> 4, c4 = i & 15;
            *(float4*)&Xs[r][c4 * 4] =
                *(const float4*)&x[(row0 + r) * Cc + k0 + c4 * 4];
            *(float4*)&Ws[r][c4 * 4] =
                *(const float4*)&W[(long)r * Cc + k0 + c4 * 4];
        }
        __syncthreads();
#pragma unroll 4
        for (int k4 = 0; k4 < 16; k4++) {
            float4 xa[4];
            float4 wb[8];
#pragma unroll
            for (int a = 0; a < 4; a++)
                xa[a] = *(const float4*)&Xs[a * 16 + ty][k4 * 4];
#pragma unroll
            for (int b = 0; b < 8; b++)
                wb[b] = *(const float4*)&Ws[b * 8 + tx][k4 * 4];
#pragma unroll
            for (int a = 0; a < 4; a++)
#pragma unroll
                for (int b = 0; b < 8; b++)
                    acc[a][b] += xa[a].x * wb[b].x + xa[a].y * wb[b].y +
                                 xa[a].z * wb[b].z + xa[a].w * wb[b].w;
        }
        __syncthreads();
    }
#pragma unroll
    for (int a = 0; a < 4; a++) {
        long r = row0 + a * 16 + ty;
#pragma unroll
        for (int b = 0; b < 8; b++)
            out[r * Hh + b * 8 + tx] = acc[a][b];
    }
}

// ---------------------------------------------------------------------------
// Flash attention, causal with diagonal offset +1.
// grid: (64 q-tiles [reversed for balance], 4 batches), 128 threads.
// S fragment: rows a*16+ty, cols b*8+tx.  O fragment: rows a*16+ty, h=tx*8+b.
// ---------------------------------------------------------------------------
struct AttnSmem {
    float Qs[64][68];
    float Ks[64][68];
    float Vs[64][68];
    float Ss[64][68];
    float mrow[64];
    float lrow[64];
    float alpha[64];
    float red[64][2];
};

__global__ __launch_bounds__(128) void attn_kernel(float* __restrict__ out)
{
    extern __shared__ char smraw[];
    AttnSmem& sm = *reinterpret_cast<AttnSmem*>(smraw);

    const int tid = threadIdx.x;
    const int tx = tid & 7;
    const int ty = tid >> 3;
    const int bb = blockIdx.y;
    const int q0 = (63 - (int)blockIdx.x) * 64;  // big tiles first

    const float* Qg = g_Q + (long)bb * Tt * Hh;
    const float* Kg = g_K + (long)bb * Tt * Hh;
    const float* Vg = g_V + (long)bb * Tt * Hh;

    // load Q tile
    for (int i = tid; i < 64 * 16; i += 128) {
        int r = i >> 4, c4 = i & 15;
        *(float4*)&sm.Qs[r][c4 * 4] =
            *(const float4*)&Qg[(long)(q0 + r) * Hh + c4 * 4];
    }
    if (tid < 64) { sm.mrow[tid] = -3.0e38f; sm.lrow[tid] = 0.f; }

    float oacc[4][8];
#pragma unroll
    for (int a = 0; a < 4; a++)
#pragma unroll
        for (int b = 0; b < 8; b++) oacc[a][b] = 0.f;

    // mask: key j visible iff j <= i+1 -> last query of tile needs one key of
    // the NEXT kv tile, hence +2 (capped at T/64).
    const int ntiles = min(q0 / 64 + 2, Tt / 64);

    for (int t = 0; t < ntiles; t++) {
        const int j0 = t * 64;
        __syncthreads();  // protect Ks/Vs/Ss reuse (and init on first iter)
        for (int i = tid; i < 64 * 16; i += 128) {
            int r = i >> 4, c4 = i & 15;
            *(float4*)&sm.Ks[r][c4 * 4] =
                *(const float4*)&Kg[(long)(j0 + r) * Hh + c4 * 4];
            *(float4*)&sm.Vs[r][c4 * 4] =
                *(const float4*)&Vg[(long)(j0 + r) * Hh + c4 * 4];
        }
        __syncthreads();

        // ---- S = Q K^T ----
        float sacc[4][8];
#pragma unroll
        for (int a = 0; a < 4; a++)
#pragma unroll
            for (int b = 0; b < 8; b++) sacc[a][b] = 0.f;
#pragma unroll 4
        for (int k4 = 0; k4 < 16; k4++) {
            float4 qa[4];
            float4 kb[8];
#pragma unroll
            for (int a = 0; a < 4; a++)
                qa[a] = *(const float4*)&sm.Qs[a * 16 + ty][k4 * 4];
#pragma unroll
            for (int b = 0; b < 8; b++)
                kb[b] = *(const float4*)&sm.Ks[b * 8 + tx][k4 * 4];
#pragma unroll
            for (int a = 0; a < 4; a++)
#pragma unroll
                for (int b = 0; b < 8; b++)
                    sacc[a][b] += qa[a].x * kb[b].x + qa[a].y * kb[b].y +
                                  qa[a].z * kb[b].z + qa[a].w * kb[b].w;
        }

        // ---- store S with mask ----
        const bool tile_masked = (j0 >= q0);
#pragma unroll
        for (int a = 0; a < 4; a++) {
            int r = a * 16 + ty;
#pragma unroll
            for (int b = 0; b < 8; b++) {
                int c = b * 8 + tx;
                float vsc = sacc[a][b];
                if (tile_masked && (j0 + c > q0 + r + 1)) vsc = -3.0e38f;
                sm.Ss[r][c] = vsc;
            }
        }
        __syncthreads();

        // ---- online softmax: row max (2 threads / row) ----
        const int r2 = tid >> 1, h2 = tid & 1;
        float mloc = -3.0e38f;
#pragma unroll 8
        for (int c = 0; c < 32; c++)
            mloc = fmaxf(mloc, sm.Ss[r2][h2 * 32 + c]);
        sm.red[r2][h2] = mloc;
        __syncthreads();
        if (tid < 64) {
            float mt = fmaxf(sm.red[tid][0], sm.red[tid][1]);
            float mo = sm.mrow[tid];
            float mn = fmaxf(mo, mt);
            sm.mrow[tid] = mn;
            sm.alpha[tid] = exp2f((mo - mn) * S2L2E);
        }
        __syncthreads();

        // rescale O accumulators
#pragma unroll
        for (int a = 0; a < 4; a++) {
            float al = sm.alpha[a * 16 + ty];
#pragma unroll
            for (int b = 0; b < 8; b++) oacc[a][b] *= al;
        }
        // P = exp(...) in-place, partial row sums
        {
            float mn = sm.mrow[r2];
            float psum = 0.f;
#pragma unroll 8
            for (int c = 0; c < 32; c++) {
                float p = exp2f((sm.Ss[r2][h2 * 32 + c] - mn) * S2L2E);
                sm.Ss[r2][h2 * 32 + c] = p;
                psum += p;
            }
            sm.red[r2][h2] = psum;
        }
        __syncthreads();
        if (tid < 64)
            sm.lrow[tid] =
                sm.lrow[tid] * sm.alpha[tid] + sm.red[tid][0] + sm.red[tid][1];

        // ---- O += P V ----
#pragma unroll 4
        for (int k4 = 0; k4 < 16; k4++) {
            float4 pa[4];
#pragma unroll
            for (int a = 0; a < 4; a++)
                pa[a] = *(const float4*)&sm.Ss[a * 16 + ty][k4 * 4];
#pragma unroll
            for (int kk = 0; kk < 4; kk++) {
                float4 v0 = *(const float4*)&sm.Vs[k4 * 4 + kk][tx * 8];
                float4 v1 = *(const float4*)&sm.Vs[k4 * 4 + kk][tx * 8 + 4];
#pragma unroll
                for (int a = 0; a < 4; a++) {
                    float p = ((const float*)&pa[a])[kk];
                    oacc[a][0] += p * v0.x;
                    oacc[a][1] += p * v0.y;
                    oacc[a][2] += p * v0.z;
                    oacc[a][3] += p * v0.w;
                    oacc[a][4] += p * v1.x;
                    oacc[a][5] += p * v1.y;
                    oacc[a][6] += p * v1.z;
                    oacc[a][7] += p * v1.w;
                }
            }
        }
    }

    __syncthreads();  // ensure final lrow update is visible
#pragma unroll
    for (int a = 0; a < 4; a++) {
        int r = a * 16 + ty;
        float inv = 1.0f / sm.lrow[r];
        float4 o0, o1;
        o0.x = oacc[a][0] * inv; o0.y = oacc[a][1] * inv;
        o0.z = oacc[a][2] * inv; o0.w = oacc[a][3] * inv;
        o1.x = oacc[a][4] * inv; o1.y = oacc[a][5] * inv;
        o1.z = oacc[a][6] * inv; o1.w = oacc[a][7] * inv;
        long base = ((long)bb * Tt + q0 + r) * Hh + tx * 8;
        *(float4*)&out[base]     = o0;
        *(float4*)&out[base + 4] = o1;
    }
}

// ---------------------------------------------------------------------------
extern "C" void kernel_launch(void* const* d_in, const int* in_sizes, int n_in,
                              void* d_out, int out_size)
{
    const float* q  = (const float*)d_in[0];
    const float* k  = (const float*)d_in[1];
    const float* v  = (const float*)d_in[2];
    const float* Wq = (const float*)d_in[3];
    const float* Wk = (const float*)d_in[4];
    const float* Wv = (const float*)d_in[5];
    float* out = (float*)d_out;

    dim3 pgrid((Bb * Tt) / 64, 1, 3);  // 256 row-tiles x 3 matrices
    proj_kernel<<<pgrid, 128>>>(q, k, v, Wq, Wk, Wv);

    cudaFuncSetAttribute(attn_kernel,
                         cudaFuncAttributeMaxDynamicSharedMemorySize,
                         (int)sizeof(AttnSmem));
    attn_kernel<<<dim3(Tt / 64, Bb), 128, sizeof(AttnSmem)>>>(out);
}

// round 3
// speedup vs baseline: 1.4999x; 1.4999x over previous
#include <cuda_runtime.h>
#include <cuda_bf16.h>
#include <cstdint>

#define Bb 4
#define Tt 4096
#define Cc 1024
#define Hh 64

// combined scale: softmax(QK^T /64); exp(x/64) = exp2(x * log2e/64)
#define S2L2E 0.022542110f

__device__ float g_Q[Bb * Tt * Hh];
__device__ float g_K[Bb * Tt * Hh];
__device__ float g_V[Bb * Tt * Hh];

// ---------------------------------------------------------------------------
// mma.sync m16n8k16 bf16 (baseline PTX, works on sm_103 without 'a' features)
// A row-major 16x16, B col-layout 16x8, C/D f32 16x8.
//   a0 = A[r][k0+0,1]   a1 = A[r+8][k0+0,1]   a2 = A[r][k0+8,9]  a3 = A[r+8][k0+8,9]
//   b0 = B[k0+0,1][n]   b1 = B[k0+8,9][n]       (r=lane/4, k0=(lane%4)*2, n=lane/4)
//   c0 = C[r][(lane%4)*2] c1 = +1  c2/c3 = row r+8
// ---------------------------------------------------------------------------
__device__ __forceinline__ void mma_bf16(float c[4], uint32_t a0, uint32_t a1,
                                         uint32_t a2, uint32_t a3,
                                         uint32_t b0, uint32_t b1) {
    asm volatile(
        "mma.sync.aligned.m16n8k16.row.col.f32.bf16.bf16.f32 "
        "{%0,%1,%2,%3}, {%4,%5,%6,%7}, {%8,%9}, {%0,%1,%2,%3};"
        : "+f"(c[0]), "+f"(c[1]), "+f"(c[2]), "+f"(c[3])
        : "r"(a0), "r"(a1), "r"(a2), "r"(a3), "r"(b0), "r"(b1));
}

__device__ __forceinline__ uint32_t packbf(float a, float b) {
    __nv_bfloat162 t;
    t.x = __float2bfloat16(a);
    t.y = __float2bfloat16(b);
    return *reinterpret_cast<uint32_t*>(&t);
}

// row stride 72 bf16 (=144B): fragment loads (8 rows x 4 word-offsets) hit
// distinct banks: bank = 4*row + off (mod 32), all distinct.
#define LDW 72

// ===========================================================================
// Projection: out[row][h] = sum_c x[row][c] * W[h][c]   (M=128/CTA, N=64, K=1024)
// grid (128,1,3), 128 threads = 4 warps, warp owns 32 rows (2 m-tiles).
// bf16x3: Xh*Wh + Xh*Wl + Xl*Wh, f32 accum.
// ===========================================================================
struct PSmem {
    __nv_bfloat16 Xh[128][LDW];
    __nv_bfloat16 Xl[128][LDW];
    __nv_bfloat16 Wh[64][LDW];
    __nv_bfloat16 Wl[64][LDW];
};

__global__ __launch_bounds__(128) void proj_kernel(
    const float* __restrict__ xq, const float* __restrict__ xk,
    const float* __restrict__ xv,
    const float* __restrict__ Wq, const float* __restrict__ Wk,
    const float* __restrict__ Wv)
{
    extern __shared__ char smraw[];
    PSmem& sm = *reinterpret_cast<PSmem*>(smraw);

    const float* x;
    const float* W;
    float* out;
    if (blockIdx.z == 0)      { x = xq; W = Wq; out = g_Q; }
    else if (blockIdx.z == 1) { x = xk; W = Wk; out = g_K; }
    else                      { x = xv; W = Wv; out = g_V; }

    const int tid = threadIdx.x;
    const int warp = tid >> 5;
    const int lane = tid & 31;
    const int lr = lane >> 2;        // fragment row within 8
    const int lc = (lane & 3) * 2;   // fragment col pair base
    const long row0 = (long)blockIdx.x * 128;

    float acc[2][8][4];
#pragma unroll
    for (int m = 0; m < 2; m++)
#pragma unroll
        for (int n = 0; n < 8; n++)
#pragma unroll
            for (int e = 0; e < 4; e++) acc[m][n][e] = 0.f;

    for (int chunk = 0; chunk < 16; chunk++) {
        const int k0 = chunk * 64;
        // stage X chunk 128x64 (hi/lo)
        for (int i = tid; i < 128 * 32; i += 128) {
            int r = i >> 5, c2 = (i & 31) * 2;
            float2 v = *(const float2*)&x[(row0 + r) * Cc + k0 + c2];
            __nv_bfloat16 h0 = __float2bfloat16(v.x);
            __nv_bfloat16 h1 = __float2bfloat16(v.y);
            sm.Xh[r][c2] = h0; sm.Xh[r][c2 + 1] = h1;
            sm.Xl[r][c2]     = __float2bfloat16(v.x - __bfloat162float(h0));
            sm.Xl[r][c2 + 1] = __float2bfloat16(v.y - __bfloat162float(h1));
        }
        // stage W chunk 64x64 (hi/lo)
        for (int i = tid; i < 64 * 32; i += 128) {
            int r = i >> 5, c2 = (i & 31) * 2;
            float2 v = *(const float2*)&W[(long)r * Cc + k0 + c2];
            __nv_bfloat16 h0 = __float2bfloat16(v.x);
            __nv_bfloat16 h1 = __float2bfloat16(v.y);
            sm.Wh[r][c2] = h0; sm.Wh[r][c2 + 1] = h1;
            sm.Wl[r][c2]     = __float2bfloat16(v.x - __bfloat162float(h0));
            sm.Wl[r][c2 + 1] = __float2bfloat16(v.y - __bfloat162float(h1));
        }
        __syncthreads();

        const int r0 = warp * 32;
#pragma unroll
        for (int s = 0; s < 4; s++) {
            const int kk = s * 16 + lc;
            uint32_t ah[2][4], al[2][4];
#pragma unroll
            for (int m = 0; m < 2; m++) {
                int rr = r0 + m * 16 + lr;
                ah[m][0] = *(const uint32_t*)&sm.Xh[rr][kk];
                ah[m][1] = *(const uint32_t*)&sm.Xh[rr + 8][kk];
                ah[m][2] = *(const uint32_t*)&sm.Xh[rr][kk + 8];
                ah[m][3] = *(const uint32_t*)&sm.Xh[rr + 8][kk + 8];
                al[m][0] = *(const uint32_t*)&sm.Xl[rr][kk];
                al[m][1] = *(const uint32_t*)&sm.Xl[rr + 8][kk];
                al[m][2] = *(const uint32_t*)&sm.Xl[rr][kk + 8];
                al[m][3] = *(const uint32_t*)&sm.Xl[rr + 8][kk + 8];
            }
#pragma unroll
            for (int n = 0; n < 8; n++) {
                int wr = n * 8 + lr;
                uint32_t bh0 = *(const uint32_t*)&sm.Wh[wr][kk];
                uint32_t bh1 = *(const uint32_t*)&sm.Wh[wr][kk + 8];
                uint32_t bl0 = *(const uint32_t*)&sm.Wl[wr][kk];
                uint32_t bl1 = *(const uint32_t*)&sm.Wl[wr][kk + 8];
#pragma unroll
                for (int m = 0; m < 2; m++) {
                    mma_bf16(acc[m][n], ah[m][0], ah[m][1], ah[m][2], ah[m][3], bh0, bh1);
                    mma_bf16(acc[m][n], ah[m][0], ah[m][1], ah[m][2], ah[m][3], bl0, bl1);
                    mma_bf16(acc[m][n], al[m][0], al[m][1], al[m][2], al[m][3], bh0, bh1);
                }
            }
        }
        __syncthreads();
    }

#pragma unroll
    for (int m = 0; m < 2; m++) {
        long rr = row0 + warp * 32 + m * 16 + lr;
#pragma unroll
        for (int n = 0; n < 8; n++) {
            int col = n * 8 + lc;
            *(float2*)&out[rr * Hh + col]       = make_float2(acc[m][n][0], acc[m][n][1]);
            *(float2*)&out[(rr + 8) * Hh + col] = make_float2(acc[m][n][2], acc[m][n][3]);
        }
    }
}

// ===========================================================================
// Flash attention, causal diag+1, bf16x3 MMA for S=QK^T and O+=P*V.
// grid (64,4) reversed, 128 threads = 4 warps, warp owns 16 q-rows.
// S c-fragment feeds the PV a-fragment directly (register-only P).
// ===========================================================================
struct ASmem {
    __nv_bfloat16 Qh[64][LDW];
    __nv_bfloat16 Ql[64][LDW];
    __nv_bfloat16 Kh[64][LDW];
    __nv_bfloat16 Kl[64][LDW];
    __nv_bfloat16 Vth[64][LDW];  // transposed: [h][kv]
    __nv_bfloat16 Vtl[64][LDW];
};

__global__ __launch_bounds__(128) void attn_kernel(float* __restrict__ out)
{
    extern __shared__ char smraw2[];
    ASmem& sm = *reinterpret_cast<ASmem*>(smraw2);

    const int tid = threadIdx.x;
    const int warp = tid >> 5;
    const int lane = tid & 31;
    const int lr = lane >> 2;
    const int lc = (lane & 3) * 2;
    const int bb = blockIdx.y;
    const int q0 = (63 - (int)blockIdx.x) * 64;

    const float* Qg = g_Q + (long)bb * Tt * Hh;
    const float* Kg = g_K + (long)bb * Tt * Hh;
    const float* Vg = g_V + (long)bb * Tt * Hh;

    // stage Q (hi/lo)
    for (int i = tid; i < 64 * 32; i += 128) {
        int r = i >> 5, c2 = (i & 31) * 2;
        float2 v = *(const float2*)&Qg[(long)(q0 + r) * Hh + c2];
        __nv_bfloat16 h0 = __float2bfloat16(v.x);
        __nv_bfloat16 h1 = __float2bfloat16(v.y);
        sm.Qh[r][c2] = h0; sm.Qh[r][c2 + 1] = h1;
        sm.Ql[r][c2]     = __float2bfloat16(v.x - __bfloat162float(h0));
        sm.Ql[r][c2 + 1] = __float2bfloat16(v.y - __bfloat162float(h1));
    }

    float m0 = -3.0e38f, m1 = -3.0e38f, l0 = 0.f, l1 = 0.f;
    float oacc[8][4];
#pragma unroll
    for (int n = 0; n < 8; n++)
#pragma unroll
        for (int e = 0; e < 4; e++) oacc[n][e] = 0.f;

    const int qrow = warp * 16 + lr;  // this thread's first q row (local)
    const int ntiles = min(q0 / 64 + 2, Tt / 64);

    for (int t = 0; t < ntiles; t++) {
        const int j0 = t * 64;
        __syncthreads();
        // stage K (hi/lo), row-major [kv][h]
        for (int i = tid; i < 64 * 32; i += 128) {
            int r = i >> 5, c2 = (i & 31) * 2;
            float2 v = *(const float2*)&Kg[(long)(j0 + r) * Hh + c2];
            __nv_bfloat16 h0 = __float2bfloat16(v.x);
            __nv_bfloat16 h1 = __float2bfloat16(v.y);
            sm.Kh[r][c2] = h0; sm.Kh[r][c2 + 1] = h1;
            sm.Kl[r][c2]     = __float2bfloat16(v.x - __bfloat162float(h0));
            sm.Kl[r][c2 + 1] = __float2bfloat16(v.y - __bfloat162float(h1));
        }
        // stage V transposed [h][kv] (hi/lo)
        for (int i = tid; i < 64 * 64; i += 128) {
            int k = i >> 6, h = i & 63;
            float v = Vg[(long)(j0 + k) * Hh + h];
            __nv_bfloat16 hv = __float2bfloat16(v);
            sm.Vth[h][k] = hv;
            sm.Vtl[h][k] = __float2bfloat16(v - __bfloat162float(hv));
        }
        __syncthreads();

        // ---- S = Q K^T (bf16x3) ----
        float sc[8][4];
#pragma unroll
        for (int n = 0; n < 8; n++)
#pragma unroll
            for (int e = 0; e < 4; e++) sc[n][e] = 0.f;
#pragma unroll
        for (int s = 0; s < 4; s++) {
            const int kk = s * 16 + lc;
            uint32_t ah0 = *(const uint32_t*)&sm.Qh[qrow][kk];
            uint32_t ah1 = *(const uint32_t*)&sm.Qh[qrow + 8][kk];
            uint32_t ah2 = *(const uint32_t*)&sm.Qh[qrow][kk + 8];
            uint32_t ah3 = *(const uint32_t*)&sm.Qh[qrow + 8][kk + 8];
            uint32_t al0 = *(const uint32_t*)&sm.Ql[qrow][kk];
            uint32_t al1 = *(const uint32_t*)&sm.Ql[qrow + 8][kk];
            uint32_t al2 = *(const uint32_t*)&sm.Ql[qrow][kk + 8];
            uint32_t al3 = *(const uint32_t*)&sm.Ql[qrow + 8][kk + 8];
#pragma unroll
            for (int n = 0; n < 8; n++) {
                int kr = n * 8 + lr;
                uint32_t bh0 = *(const uint32_t*)&sm.Kh[kr][kk];
                uint32_t bh1 = *(const uint32_t*)&sm.Kh[kr][kk + 8];
                uint32_t bl0 = *(const uint32_t*)&sm.Kl[kr][kk];
                uint32_t bl1 = *(const uint32_t*)&sm.Kl[kr][kk + 8];
                mma_bf16(sc[n], ah0, ah1, ah2, ah3, bh0, bh1);
                mma_bf16(sc[n], ah0, ah1, ah2, ah3, bl0, bl1);
                mma_bf16(sc[n], al0, al1, al2, al3, bh0, bh1);
            }
        }

        // ---- causal mask (diag offset +1) ----
        if (j0 >= q0) {
            const int i0 = q0 + qrow;
#pragma unroll
            for (int n = 0; n < 8; n++) {
                int j = j0 + n * 8 + lc;
                if (j     > i0 + 1)     sc[n][0] = -3.0e38f;
                if (j + 1 > i0 + 1)     sc[n][1] = -3.0e38f;
                if (j     > i0 + 9)     sc[n][2] = -3.0e38f;
                if (j + 1 > i0 + 9)     sc[n][3] = -3.0e38f;
            }
        }

        // ---- register online softmax (rows: lanes sharing lane/4) ----
        float rmax0 = -3.0e38f, rmax1 = -3.0e38f;
#pragma unroll
        for (int n = 0; n < 8; n++) {
            rmax0 = fmaxf(rmax0, fmaxf(sc[n][0], sc[n][1]));
            rmax1 = fmaxf(rmax1, fmaxf(sc[n][2], sc[n][3]));
        }
        rmax0 = fmaxf(rmax0, __shfl_xor_sync(0xffffffffu, rmax0, 1));
        rmax0 = fmaxf(rmax0, __shfl_xor_sync(0xffffffffu, rmax0, 2));
        rmax1 = fmaxf(rmax1, __shfl_xor_sync(0xffffffffu, rmax1, 1));
        rmax1 = fmaxf(rmax1, __shfl_xor_sync(0xffffffffu, rmax1, 2));
        float mn0 = fmaxf(m0, rmax0), mn1 = fmaxf(m1, rmax1);
        float alpha0 = exp2f((m0 - mn0) * S2L2E);
        float alpha1 = exp2f((m1 - mn1) * S2L2E);
        m0 = mn0; m1 = mn1;
        float ps0 = 0.f, ps1 = 0.f;
#pragma unroll
        for (int n = 0; n < 8; n++) {
            sc[n][0] = exp2f((sc[n][0] - mn0) * S2L2E);
            sc[n][1] = exp2f((sc[n][1] - mn0) * S2L2E);
            sc[n][2] = exp2f((sc[n][2] - mn1) * S2L2E);
            sc[n][3] = exp2f((sc[n][3] - mn1) * S2L2E);
            ps0 += sc[n][0] + sc[n][1];
            ps1 += sc[n][2] + sc[n][3];
        }
        ps0 += __shfl_xor_sync(0xffffffffu, ps0, 1);
        ps0 += __shfl_xor_sync(0xffffffffu, ps0, 2);
        ps1 += __shfl_xor_sync(0xffffffffu, ps1, 1);
        ps1 += __shfl_xor_sync(0xffffffffu, ps1, 2);
        l0 = l0 * alpha0 + ps0;
        l1 = l1 * alpha1 + ps1;
#pragma unroll
        for (int n = 0; n < 8; n++) {
            oacc[n][0] *= alpha0; oacc[n][1] *= alpha0;
            oacc[n][2] *= alpha1; oacc[n][3] *= alpha1;
        }

        // ---- O += P V (bf16x3); P fragments built in-register from sc ----
#pragma unroll
        for (int s = 0; s < 4; s++) {
            const int t0 = 2 * s, t1 = 2 * s + 1;
            uint32_t ph0 = packbf(sc[t0][0], sc[t0][1]);
            uint32_t ph1 = packbf(sc[t0][2], sc[t0][3]);
            uint32_t ph2 = packbf(sc[t1][0], sc[t1][1]);
            uint32_t ph3 = packbf(sc[t1][2], sc[t1][3]);
            // residuals
            __nv_bfloat162* hp;
            uint32_t pl0, pl1, pl2, pl3;
            {
                hp = (__nv_bfloat162*)&ph0;
                pl0 = packbf(sc[t0][0] - __bfloat162float(hp->x),
                             sc[t0][1] - __bfloat162float(hp->y));
                hp = (__nv_bfloat162*)&ph1;
                pl1 = packbf(sc[t0][2] - __bfloat162float(hp->x),
                             sc[t0][3] - __bfloat162float(hp->y));
                hp = (__nv_bfloat162*)&ph2;
                pl2 = packbf(sc[t1][0] - __bfloat162float(hp->x),
                             sc[t1][1] - __bfloat162float(hp->y));
                hp = (__nv_bfloat162*)&ph3;
                pl3 = packbf(sc[t1][2] - __bfloat162float(hp->x),
                             sc[t1][3] - __bfloat162float(hp->y));
            }
            const int kk = s * 16 + lc;
#pragma unroll
            for (int n = 0; n < 8; n++) {
                int vr = n * 8 + lr;
                uint32_t bh0 = *(const uint32_t*)&sm.Vth[vr][kk];
                uint32_t bh1 = *(const uint32_t*)&sm.Vth[vr][kk + 8];
                uint32_t bl0 = *(const uint32_t*)&sm.Vtl[vr][kk];
                uint32_t bl1 = *(const uint32_t*)&sm.Vtl[vr][kk + 8];
                mma_bf16(oacc[n], ph0, ph1, ph2, ph3, bh0, bh1);
                mma_bf16(oacc[n], ph0, ph1, ph2, ph3, bl0, bl1);
                mma_bf16(oacc[n], pl0, pl1, pl2, pl3, bh0, bh1);
            }
        }
    }

    // ---- epilogue ----
    const float inv0 = 1.0f / l0;
    const float inv1 = 1.0f / l1;
    const long rbase = (long)bb * Tt + q0 + qrow;
#pragma unroll
    for (int n = 0; n < 8; n++) {
        int col = n * 8 + lc;
        *(float2*)&out[rbase * Hh + col] =
            make_float2(oacc[n][0] * inv0, oacc[n][1] * inv0);
        *(float2*)&out[(rbase + 8) * Hh + col] =
            make_float2(oacc[n][2] * inv1, oacc[n][3] * inv1);
    }
}

// ===========================================================================
extern "C" void kernel_launch(void* const* d_in, const int* in_sizes, int n_in,
                              void* d_out, int out_size)
{
    const float* q  = (const float*)d_in[0];
    const float* k  = (const float*)d_in[1];
    const float* v  = (const float*)d_in[2];
    const float* Wq = (const float*)d_in[3];
    const float* Wk = (const float*)d_in[4];
    const float* Wv = (const float*)d_in[5];
    float* out = (float*)d_out;

    static int configured = 0;
    if (!configured) {
        cudaFuncSetAttribute(proj_kernel,
                             cudaFuncAttributeMaxDynamicSharedMemorySize,
                             (int)sizeof(PSmem));
        cudaFuncSetAttribute(attn_kernel,
                             cudaFuncAttributeMaxDynamicSharedMemorySize,
                             (int)sizeof(ASmem));
        configured = 1;
    }

    dim3 pgrid((Bb * Tt) / 128, 1, 3);
    proj_kernel<<<pgrid, 128, sizeof(PSmem)>>>(q, k, v, Wq, Wk, Wv);
    attn_kernel<<<dim3(Tt / 64, Bb), 128, sizeof(ASmem)>>>(out);
}

// round 4
// speedup vs baseline: 2.6951x; 1.7968x over previous
#include <cuda_runtime.h>
#include <cuda_bf16.h>
#include <cstdint>

#define Bb 4
#define Tt 4096
#define Cc 1024
#define Hh 64

// combined scale: softmax(QK^T /64); exp(x/64) = exp2(x * log2e/64)
#define S2L2E 0.022542110f

// kv tiles (of 64) per chunk, max chunks per q-tile, chunks per batch
#define CHUNK 8
#define MAXC 8
#define NCHUNKS 295   // sum over tq=0..63 of ceil(min(tq+2,64)/8)

__device__ float g_Q[Bb * Tt * Hh];
__device__ float g_K[Bb * Tt * Hh];
__device__ float g_V[Bb * Tt * Hh];

// split-KV partials
__device__ float g_Opart[Bb * 64 * MAXC * 64 * 64];  // ~33.5 MB
__device__ float g_Mpart[Bb * 64 * MAXC * 64];
__device__ float g_Lpart[Bb * 64 * MAXC * 64];

// ---------------------------------------------------------------------------
// mma.sync m16n8k16 bf16 (baseline PTX, no sm_103a-only features)
// ---------------------------------------------------------------------------
__device__ __forceinline__ void mma_bf16(float c[4], uint32_t a0, uint32_t a1,
                                         uint32_t a2, uint32_t a3,
                                         uint32_t b0, uint32_t b1) {
    asm volatile(
        "mma.sync.aligned.m16n8k16.row.col.f32.bf16.bf16.f32 "
        "{%0,%1,%2,%3}, {%4,%5,%6,%7}, {%8,%9}, {%0,%1,%2,%3};"
        : "+f"(c[0]), "+f"(c[1]), "+f"(c[2]), "+f"(c[3])
        : "r"(a0), "r"(a1), "r"(a2), "r"(a3), "r"(b0), "r"(b1));
}

__device__ __forceinline__ uint32_t packbf(float a, float b) {
    __nv_bfloat162 t;
    t.x = __float2bfloat16(a);
    t.y = __float2bfloat16(b);
    return *reinterpret_cast<uint32_t*>(&t);
}

#define LDW 72  // row stride in bf16 (144B) -> conflict-free fragment LDS

// ===========================================================================
// Projection (unchanged from R3): bf16x3 MMA, M=128/CTA, N=64, K=1024
// ===========================================================================
struct PSmem {
    __nv_bfloat16 Xh[128][LDW];
    __nv_bfloat16 Xl[128][LDW];
    __nv_bfloat16 Wh[64][LDW];
    __nv_bfloat16 Wl[64][LDW];
};

__global__ __launch_bounds__(128) void proj_kernel(
    const float* __restrict__ xq, const float* __restrict__ xk,
    const float* __restrict__ xv,
    const float* __restrict__ Wq, const float* __restrict__ Wk,
    const float* __restrict__ Wv)
{
    extern __shared__ char smraw[];
    PSmem& sm = *reinterpret_cast<PSmem*>(smraw);

    const float* x;
    const float* W;
    float* out;
    if (blockIdx.z == 0)      { x = xq; W = Wq; out = g_Q; }
    else if (blockIdx.z == 1) { x = xk; W = Wk; out = g_K; }
    else                      { x = xv; W = Wv; out = g_V; }

    const int tid = threadIdx.x;
    const int warp = tid >> 5;
    const int lane = tid & 31;
    const int lr = lane >> 2;
    const int lc = (lane & 3) * 2;
    const long row0 = (long)blockIdx.x * 128;

    float acc[2][8][4];
#pragma unroll
    for (int m = 0; m < 2; m++)
#pragma unroll
        for (int n = 0; n < 8; n++)
#pragma unroll
            for (int e = 0; e < 4; e++) acc[m][n][e] = 0.f;

    for (int chunk = 0; chunk < 16; chunk++) {
        const int k0 = chunk * 64;
        for (int i = tid; i < 128 * 32; i += 128) {
            int r = i >> 5, c2 = (i & 31) * 2;
            float2 v = *(const float2*)&x[(row0 + r) * Cc + k0 + c2];
            __nv_bfloat16 h0 = __float2bfloat16(v.x);
            __nv_bfloat16 h1 = __float2bfloat16(v.y);
            sm.Xh[r][c2] = h0; sm.Xh[r][c2 + 1] = h1;
            sm.Xl[r][c2]     = __float2bfloat16(v.x - __bfloat162float(h0));
            sm.Xl[r][c2 + 1] = __float2bfloat16(v.y - __bfloat162float(h1));
        }
        for (int i = tid; i < 64 * 32; i += 128) {
            int r = i >> 5, c2 = (i & 31) * 2;
            float2 v = *(const float2*)&W[(long)r * Cc + k0 + c2];
            __nv_bfloat16 h0 = __float2bfloat16(v.x);
            __nv_bfloat16 h1 = __float2bfloat16(v.y);
            sm.Wh[r][c2] = h0; sm.Wh[r][c2 + 1] = h1;
            sm.Wl[r][c2]     = __float2bfloat16(v.x - __bfloat162float(h0));
            sm.Wl[r][c2 + 1] = __float2bfloat16(v.y - __bfloat162float(h1));
        }
        __syncthreads();

        const int r0 = warp * 32;
#pragma unroll
        for (int s = 0; s < 4; s++) {
            const int kk = s * 16 + lc;
            uint32_t ah[2][4], al[2][4];
#pragma unroll
            for (int m = 0; m < 2; m++) {
                int rr = r0 + m * 16 + lr;
                ah[m][0] = *(const uint32_t*)&sm.Xh[rr][kk];
                ah[m][1] = *(const uint32_t*)&sm.Xh[rr + 8][kk];
                ah[m][2] = *(const uint32_t*)&sm.Xh[rr][kk + 8];
                ah[m][3] = *(const uint32_t*)&sm.Xh[rr + 8][kk + 8];
                al[m][0] = *(const uint32_t*)&sm.Xl[rr][kk];
                al[m][1] = *(const uint32_t*)&sm.Xl[rr + 8][kk];
                al[m][2] = *(const uint32_t*)&sm.Xl[rr][kk + 8];
                al[m][3] = *(const uint32_t*)&sm.Xl[rr + 8][kk + 8];
            }
#pragma unroll
            for (int n = 0; n < 8; n++) {
                int wr = n * 8 + lr;
                uint32_t bh0 = *(const uint32_t*)&sm.Wh[wr][kk];
                uint32_t bh1 = *(const uint32_t*)&sm.Wh[wr][kk + 8];
                uint32_t bl0 = *(const uint32_t*)&sm.Wl[wr][kk];
                uint32_t bl1 = *(const uint32_t*)&sm.Wl[wr][kk + 8];
#pragma unroll
                for (int m = 0; m < 2; m++) {
                    mma_bf16(acc[m][n], ah[m][0], ah[m][1], ah[m][2], ah[m][3], bh0, bh1);
                    mma_bf16(acc[m][n], ah[m][0], ah[m][1], ah[m][2], ah[m][3], bl0, bl1);
                    mma_bf16(acc[m][n], al[m][0], al[m][1], al[m][2], al[m][3], bh0, bh1);
                }
            }
        }
        __syncthreads();
    }

#pragma unroll
    for (int m = 0; m < 2; m++) {
        long rr = row0 + warp * 32 + m * 16 + lr;
#pragma unroll
        for (int n = 0; n < 8; n++) {
            int col = n * 8 + lc;
            *(float2*)&out[rr * Hh + col]       = make_float2(acc[m][n][0], acc[m][n][1]);
            *(float2*)&out[(rr + 8) * Hh + col] = make_float2(acc[m][n][2], acc[m][n][3]);
        }
    }
}

// ===========================================================================
// Phase 1: split-KV flash attention. One CTA per (b, q-tile, kv-chunk).
// Writes unnormalized partial O + per-row (m, l) to scratch.
// ===========================================================================
struct ASmem {
    __nv_bfloat16 Qh[64][LDW];
    __nv_bfloat16 Ql[64][LDW];
    __nv_bfloat16 Kh[64][LDW];
    __nv_bfloat16 Kl[64][LDW];
    __nv_bfloat16 Vth[64][LDW];  // transposed [h][kv]
    __nv_bfloat16 Vtl[64][LDW];
};

__global__ __launch_bounds__(128, 4) void attn_kernel()
{
    extern __shared__ char smraw2[];
    ASmem& sm = *reinterpret_cast<ASmem*>(smraw2);

    const int tid = threadIdx.x;
    const int warp = tid >> 5;
    const int lane = tid & 31;
    const int lr = lane >> 2;
    const int lc = (lane & 3) * 2;
    const int bb = blockIdx.y;

    // flat chunk index -> (tq, c)
    int rem = blockIdx.x;
    int tq = 0;
#pragma unroll 1
    for (; tq < 64; tq++) {
        int nt = min(tq + 2, 64);
        int nc = (nt + CHUNK - 1) >> 3;
        if (rem < nc) break;
        rem -= nc;
    }
    const int c = rem;
    const int q0 = tq * 64;
    const int ntiles = min(tq + 2, Tt / 64);
    const int tstart = c * CHUNK;
    const int tend = min(tstart + CHUNK, ntiles);

    const float* Qg = g_Q + (long)bb * Tt * Hh;
    const float* Kg = g_K + (long)bb * Tt * Hh;
    const float* Vg = g_V + (long)bb * Tt * Hh;

    // stage Q (hi/lo)
    for (int i = tid; i < 64 * 32; i += 128) {
        int r = i >> 5, c2 = (i & 31) * 2;
        float2 v = *(const float2*)&Qg[(long)(q0 + r) * Hh + c2];
        __nv_bfloat16 h0 = __float2bfloat16(v.x);
        __nv_bfloat16 h1 = __float2bfloat16(v.y);
        sm.Qh[r][c2] = h0; sm.Qh[r][c2 + 1] = h1;
        sm.Ql[r][c2]     = __float2bfloat16(v.x - __bfloat162float(h0));
        sm.Ql[r][c2 + 1] = __float2bfloat16(v.y - __bfloat162float(h1));
    }

    float m0 = -3.0e38f, m1 = -3.0e38f, l0 = 0.f, l1 = 0.f;
    float oacc[8][4];
#pragma unroll
    for (int n = 0; n < 8; n++)
#pragma unroll
        for (int e = 0; e < 4; e++) oacc[n][e] = 0.f;

    const int qrow = warp * 16 + lr;

    for (int t = tstart; t < tend; t++) {
        const int j0 = t * 64;
        __syncthreads();
        for (int i = tid; i < 64 * 32; i += 128) {
            int r = i >> 5, c2 = (i & 31) * 2;
            float2 v = *(const float2*)&Kg[(long)(j0 + r) * Hh + c2];
            __nv_bfloat16 h0 = __float2bfloat16(v.x);
            __nv_bfloat16 h1 = __float2bfloat16(v.y);
            sm.Kh[r][c2] = h0; sm.Kh[r][c2 + 1] = h1;
            sm.Kl[r][c2]     = __float2bfloat16(v.x - __bfloat162float(h0));
            sm.Kl[r][c2 + 1] = __float2bfloat16(v.y - __bfloat162float(h1));
        }
        for (int i = tid; i < 64 * 64; i += 128) {
            int k = i >> 6, h = i & 63;
            float v = Vg[(long)(j0 + k) * Hh + h];
            __nv_bfloat16 hv = __float2bfloat16(v);
            sm.Vth[h][k] = hv;
            sm.Vtl[h][k] = __float2bfloat16(v - __bfloat162float(hv));
        }
        __syncthreads();

        // ---- S = Q K^T (bf16x3) ----
        float sc[8][4];
#pragma unroll
        for (int n = 0; n < 8; n++)
#pragma unroll
            for (int e = 0; e < 4; e++) sc[n][e] = 0.f;
#pragma unroll
        for (int s = 0; s < 4; s++) {
            const int kk = s * 16 + lc;
            uint32_t ah0 = *(const uint32_t*)&sm.Qh[qrow][kk];
            uint32_t ah1 = *(const uint32_t*)&sm.Qh[qrow + 8][kk];
            uint32_t ah2 = *(const uint32_t*)&sm.Qh[qrow][kk + 8];
            uint32_t ah3 = *(const uint32_t*)&sm.Qh[qrow + 8][kk + 8];
            uint32_t al0 = *(const uint32_t*)&sm.Ql[qrow][kk];
            uint32_t al1 = *(const uint32_t*)&sm.Ql[qrow + 8][kk];
            uint32_t al2 = *(const uint32_t*)&sm.Ql[qrow][kk + 8];
            uint32_t al3 = *(const uint32_t*)&sm.Ql[qrow + 8][kk + 8];
#pragma unroll
            for (int n = 0; n < 8; n++) {
                int kr = n * 8 + lr;
                uint32_t bh0 = *(const uint32_t*)&sm.Kh[kr][kk];
                uint32_t bh1 = *(const uint32_t*)&sm.Kh[kr][kk + 8];
                uint32_t bl0 = *(const uint32_t*)&sm.Kl[kr][kk];
                uint32_t bl1 = *(const uint32_t*)&sm.Kl[kr][kk + 8];
                mma_bf16(sc[n], ah0, ah1, ah2, ah3, bh0, bh1);
                mma_bf16(sc[n], ah0, ah1, ah2, ah3, bl0, bl1);
                mma_bf16(sc[n], al0, al1, al2, al3, bh0, bh1);
            }
        }

        // ---- causal mask (diag offset +1) ----
        if (j0 >= q0) {
            const int i0 = q0 + qrow;
#pragma unroll
            for (int n = 0; n < 8; n++) {
                int j = j0 + n * 8 + lc;
                if (j     > i0 + 1) sc[n][0] = -3.0e38f;
                if (j + 1 > i0 + 1) sc[n][1] = -3.0e38f;
                if (j     > i0 + 9) sc[n][2] = -3.0e38f;
                if (j + 1 > i0 + 9) sc[n][3] = -3.0e38f;
            }
        }

        // ---- register online softmax ----
        float rmax0 = -3.0e38f, rmax1 = -3.0e38f;
#pragma unroll
        for (int n = 0; n < 8; n++) {
            rmax0 = fmaxf(rmax0, fmaxf(sc[n][0], sc[n][1]));
            rmax1 = fmaxf(rmax1, fmaxf(sc[n][2], sc[n][3]));
        }
        rmax0 = fmaxf(rmax0, __shfl_xor_sync(0xffffffffu, rmax0, 1));
        rmax0 = fmaxf(rmax0, __shfl_xor_sync(0xffffffffu, rmax0, 2));
        rmax1 = fmaxf(rmax1, __shfl_xor_sync(0xffffffffu, rmax1, 1));
        rmax1 = fmaxf(rmax1, __shfl_xor_sync(0xffffffffu, rmax1, 2));
        float mn0 = fmaxf(m0, rmax0), mn1 = fmaxf(m1, rmax1);
        float alpha0 = exp2f((m0 - mn0) * S2L2E);
        float alpha1 = exp2f((m1 - mn1) * S2L2E);
        m0 = mn0; m1 = mn1;
        // safe base: fully-masked rows (mn = -3e38) must produce p = 0
        const float me0 = fmaxf(mn0, -1.0e30f);
        const float me1 = fmaxf(mn1, -1.0e30f);
        float ps0 = 0.f, ps1 = 0.f;
#pragma unroll
        for (int n = 0; n < 8; n++) {
            sc[n][0] = exp2f((sc[n][0] - me0) * S2L2E);
            sc[n][1] = exp2f((sc[n][1] - me0) * S2L2E);
            sc[n][2] = exp2f((sc[n][2] - me1) * S2L2E);
            sc[n][3] = exp2f((sc[n][3] - me1) * S2L2E);
            ps0 += sc[n][0] + sc[n][1];
            ps1 += sc[n][2] + sc[n][3];
        }
        ps0 += __shfl_xor_sync(0xffffffffu, ps0, 1);
        ps0 += __shfl_xor_sync(0xffffffffu, ps0, 2);
        ps1 += __shfl_xor_sync(0xffffffffu, ps1, 1);
        ps1 += __shfl_xor_sync(0xffffffffu, ps1, 2);
        l0 = l0 * alpha0 + ps0;
        l1 = l1 * alpha1 + ps1;
#pragma unroll
        for (int n = 0; n < 8; n++) {
            oacc[n][0] *= alpha0; oacc[n][1] *= alpha0;
            oacc[n][2] *= alpha1; oacc[n][3] *= alpha1;
        }

        // ---- O += P V (bf16x3), register-only P ----
#pragma unroll
        for (int s = 0; s < 4; s++) {
            const int t0 = 2 * s, t1 = 2 * s + 1;
            uint32_t ph0 = packbf(sc[t0][0], sc[t0][1]);
            uint32_t ph1 = packbf(sc[t0][2], sc[t0][3]);
            uint32_t ph2 = packbf(sc[t1][0], sc[t1][1]);
            uint32_t ph3 = packbf(sc[t1][2], sc[t1][3]);
            __nv_bfloat162* hp;
            uint32_t pl0, pl1, pl2, pl3;
            hp = (__nv_bfloat162*)&ph0;
            pl0 = packbf(sc[t0][0] - __bfloat162float(hp->x),
                         sc[t0][1] - __bfloat162float(hp->y));
            hp = (__nv_bfloat162*)&ph1;
            pl1 = packbf(sc[t0][2] - __bfloat162float(hp->x),
                         sc[t0][3] - __bfloat162float(hp->y));
            hp = (__nv_bfloat162*)&ph2;
            pl2 = packbf(sc[t1][0] - __bfloat162float(hp->x),
                         sc[t1][1] - __bfloat162float(hp->y));
            hp = (__nv_bfloat162*)&ph3;
            pl3 = packbf(sc[t1][2] - __bfloat162float(hp->x),
                         sc[t1][3] - __bfloat162float(hp->y));
            const int kk = s * 16 + lc;
#pragma unroll
            for (int n = 0; n < 8; n++) {
                int vr = n * 8 + lr;
                uint32_t bh0 = *(const uint32_t*)&sm.Vth[vr][kk];
                uint32_t bh1 = *(const uint32_t*)&sm.Vth[vr][kk + 8];
                uint32_t bl0 = *(const uint32_t*)&sm.Vtl[vr][kk];
                uint32_t bl1 = *(const uint32_t*)&sm.Vtl[vr][kk + 8];
                mma_bf16(oacc[n], ph0, ph1, ph2, ph3, bh0, bh1);
                mma_bf16(oacc[n], ph0, ph1, ph2, ph3, bl0, bl1);
                mma_bf16(oacc[n], pl0, pl1, pl2, pl3, bh0, bh1);
            }
        }
    }

    // ---- write partials (unnormalized O, m, l) ----
    const long pbase = (((long)bb * 64 + tq) * MAXC + c) * 64;
    float* Op = g_Opart + pbase * 64;
#pragma unroll
    for (int n = 0; n < 8; n++) {
        int col = n * 8 + lc;
        *(float2*)&Op[(long)qrow * 64 + col] = make_float2(oacc[n][0], oacc[n][1]);
        *(float2*)&Op[(long)(qrow + 8) * 64 + col] = make_float2(oacc[n][2], oacc[n][3]);
    }
    if ((lane & 3) == 0) {
        g_Mpart[pbase + qrow] = m0;
        g_Mpart[pbase + qrow + 8] = m1;
        g_Lpart[pbase + qrow] = l0;
        g_Lpart[pbase + qrow + 8] = l1;
    }
}

// ===========================================================================
// Phase 2: merge partials. grid (64 q-tiles, 4 batches), 256 threads.
// Thread t: row = t/4, col group = (t%4)*16.
// ===========================================================================
__global__ __launch_bounds__(256) void merge_kernel(float* __restrict__ out)
{
    const int tid = threadIdx.x;
    const int r = tid >> 2;
    const int cg = (tid & 3) * 16;
    const int tq = blockIdx.x;
    const int bb = blockIdx.y;

    const int ntiles = min(tq + 2, Tt / 64);
    const int nc = (ntiles + CHUNK - 1) >> 3;
    const long base = ((long)bb * 64 + tq) * MAXC;

    float M = -3.0e38f;
    for (int c = 0; c < nc; c++)
        M = fmaxf(M, g_Mpart[(base + c) * 64 + r]);

    float acc[16];
#pragma unroll
    for (int i = 0; i < 16; i++) acc[i] = 0.f;
    float ltot = 0.f;

    for (int c = 0; c < nc; c++) {
        float mc = g_Mpart[(base + c) * 64 + r];
        float w = exp2f((mc - M) * S2L2E);
        ltot += w * g_Lpart[(base + c) * 64 + r];
        const float* Op = g_Opart + ((base + c) * 64 + r) * 64 + cg;
#pragma unroll
        for (int i = 0; i < 4; i++) {
            float4 v = *(const float4*)&Op[i * 4];
            acc[i * 4 + 0] += w * v.x;
            acc[i * 4 + 1] += w * v.y;
            acc[i * 4 + 2] += w * v.z;
            acc[i * 4 + 3] += w * v.w;
        }
    }

    const float inv = 1.0f / ltot;
    float* orow = out + ((long)bb * Tt + tq * 64 + r) * Hh + cg;
#pragma unroll
    for (int i = 0; i < 4; i++) {
        float4 o;
        o.x = acc[i * 4 + 0] * inv;
        o.y = acc[i * 4 + 1] * inv;
        o.z = acc[i * 4 + 2] * inv;
        o.w = acc[i * 4 + 3] * inv;
        *(float4*)&orow[i * 4] = o;
    }
}

// ===========================================================================
extern "C" void kernel_launch(void* const* d_in, const int* in_sizes, int n_in,
                              void* d_out, int out_size)
{
    const float* q  = (const float*)d_in[0];
    const float* k  = (const float*)d_in[1];
    const float* v  = (const float*)d_in[2];
    const float* Wq = (const float*)d_in[3];
    const float* Wk = (const float*)d_in[4];
    const float* Wv = (const float*)d_in[5];
    float* out = (float*)d_out;

    static int configured = 0;
    if (!configured) {
        cudaFuncSetAttribute(proj_kernel,
                             cudaFuncAttributeMaxDynamicSharedMemorySize,
                             (int)sizeof(PSmem));
        cudaFuncSetAttribute(attn_kernel,
                             cudaFuncAttributeMaxDynamicSharedMemorySize,
                             (int)sizeof(ASmem));
        configured = 1;
    }

    dim3 pgrid((Bb * Tt) / 128, 1, 3);
    proj_kernel<<<pgrid, 128, sizeof(PSmem)>>>(q, k, v, Wq, Wk, Wv);
    attn_kernel<<<dim3(NCHUNKS, Bb), 128, sizeof(ASmem)>>>();
    merge_kernel<<<dim3(Tt / 64, Bb), 256>>>(out);
}

// round 7
// speedup vs baseline: 3.4768x; 1.2900x over previous
#include <cuda_runtime.h>
#include <cuda_bf16.h>
#include <cstdint>

#define Bb 4
#define Tt 4096
#define Cc 1024
#define Hh 64

// combined scale: softmax(QK^T /64); exp(x/64) = exp2(x * log2e/64)
#define S2L2E 0.022542110f

#define CHUNK 8
#define MAXC 8
#define NCHUNKS 295

__device__ float g_Q[Bb * Tt * Hh];
__device__ float g_K[Bb * Tt * Hh];
__device__ float g_V[Bb * Tt * Hh];

__device__ float g_Opart[Bb * 64 * MAXC * 64 * 64];
__device__ float g_Mpart[Bb * 64 * MAXC * 64];
__device__ float g_Lpart[Bb * 64 * MAXC * 64];

// ---------------------------------------------------------------------------
__device__ __forceinline__ void mma_bf16(float c[4], uint32_t a0, uint32_t a1,
                                         uint32_t a2, uint32_t a3,
                                         uint32_t b0, uint32_t b1) {
    asm volatile(
        "mma.sync.aligned.m16n8k16.row.col.f32.bf16.bf16.f32 "
        "{%0,%1,%2,%3}, {%4,%5,%6,%7}, {%8,%9}, {%0,%1,%2,%3};"
        : "+f"(c[0]), "+f"(c[1]), "+f"(c[2]), "+f"(c[3])
        : "r"(a0), "r"(a1), "r"(a2), "r"(a3), "r"(b0), "r"(b1));
}

__device__ __forceinline__ uint32_t packbf(float a, float b) {
    __nv_bfloat162 t;
    t.x = __float2bfloat16(a);
    t.y = __float2bfloat16(b);
    return *reinterpret_cast<uint32_t*>(&t);
}

// fp32 pair -> packed bf16 hi and packed bf16 lo (residual)
__device__ __forceinline__ void cvt_hilo(float2 v, uint32_t& hi, uint32_t& lo) {
    asm("cvt.rn.bf16x2.f32 %0, %1, %2;" : "=r"(hi) : "f"(v.y), "f"(v.x));
    __nv_bfloat162 h = *reinterpret_cast<__nv_bfloat162*>(&hi);
    float lx = v.x - __bfloat162float(h.x);
    float ly = v.y - __bfloat162float(h.y);
    asm("cvt.rn.bf16x2.f32 %0, %1, %2;" : "=r"(lo) : "f"(ly), "f"(lx));
}

__device__ __forceinline__ void cp16(uint32_t saddr, const void* gaddr) {
    asm volatile("cp.async.cg.shared.global [%0], [%1], 16;"
                 :: "r"(saddr), "l"(gaddr) : "memory");
}
#define CP_COMMIT() asm volatile("cp.async.commit_group;" ::: "memory")
#define CP_WAIT0()  asm volatile("cp.async.wait_group 0;" ::: "memory")

__device__ __forceinline__ uint32_t smem_u32(const void* p) {
    uint32_t a;
    asm("{ .reg .u64 t; cvta.to.shared.u64 t, %1; cvt.u32.u64 %0, t; }"
        : "=r"(a) : "l"(p));
    return a;
}

#define LDW 72    // bf16 stride for attn smem (144B)
#define LDF 72    // fp32 stride for proj smem (288B; 72 mod 32 = 8 -> conflict-free frags)

// ===========================================================================
// Projection: cp.async double-buffered fp32 staging + in-register bf16x3.
// grid (128,1,3), 128 threads. M=128/CTA, N=64, K=1024 in 16 chunks of 64.
// ===========================================================================
struct PBuf {
    float Xs[128][LDF];   // 36864 B
    float Ws[64][LDF];    // 18432 B
};                        // 55296 B; x2 buffers = 110592 B

__global__ __launch_bounds__(128, 2) void proj_kernel(
    const float* __restrict__ xq, const float* __restrict__ xk,
    const float* __restrict__ xv,
    const float* __restrict__ Wq, const float* __restrict__ Wk,
    const float* __restrict__ Wv)
{
    extern __shared__ char smraw[];
    PBuf* buf = reinterpret_cast<PBuf*>(smraw);

    const float* x;
    const float* W;
    float* out;
    if (blockIdx.z == 0)      { x = xq; W = Wq; out = g_Q; }
    else if (blockIdx.z == 1) { x = xk; W = Wk; out = g_K; }
    else                      { x = xv; W = Wv; out = g_V; }

    const int tid = threadIdx.x;
    const int warp = tid >> 5;
    const int lane = tid & 31;
    const int lr = lane >> 2;
    const int lc = (lane & 3) * 2;
    const long row0 = (long)blockIdx.x * 128;

    float acc[2][8][4];
#pragma unroll
    for (int m = 0; m < 2; m++)
#pragma unroll
        for (int n = 0; n < 8; n++)
#pragma unroll
            for (int e = 0; e < 4; e++) acc[m][n][e] = 0.f;

    // issue chunk 0 loads
    {
        const uint32_t xb = smem_u32(&buf[0].Xs[0][0]);
        const uint32_t wb = smem_u32(&buf[0].Ws[0][0]);
#pragma unroll
        for (int i = 0; i < 16; i++) {       // X: 2048 16B segs / 128 thr
            int idx = tid + i * 128;
            int r = idx >> 4, seg = idx & 15;
            cp16(xb + (uint32_t)(r * LDF + seg * 4) * 4,
                 &x[(row0 + r) * Cc + 0 + seg * 4]);
        }
#pragma unroll
        for (int i = 0; i < 8; i++) {        // W: 1024 segs
            int idx = tid + i * 128;
            int r = idx >> 4, seg = idx & 15;
            cp16(wb + (uint32_t)(r * LDF + seg * 4) * 4,
                 &W[(long)r * Cc + 0 + seg * 4]);
        }
        CP_COMMIT();
    }

    for (int chunk = 0; chunk < 16; chunk++) {
        const PBuf& cur = buf[chunk & 1];
        CP_WAIT0();
        __syncthreads();   // data arrived everywhere + prev reads of other buf done

        if (chunk < 15) {
            const int k0 = (chunk + 1) * 64;
            PBuf& nxt = buf[(chunk + 1) & 1];
            const uint32_t xb = smem_u32(&nxt.Xs[0][0]);
            const uint32_t wb = smem_u32(&nxt.Ws[0][0]);
#pragma unroll
            for (int i = 0; i < 16; i++) {
                int idx = tid + i * 128;
                int r = idx >> 4, seg = idx & 15;
                cp16(xb + (uint32_t)(r * LDF + seg * 4) * 4,
                     &x[(row0 + r) * Cc + k0 + seg * 4]);
            }
#pragma unroll
            for (int i = 0; i < 8; i++) {
                int idx = tid + i * 128;
                int r = idx >> 4, seg = idx & 15;
                cp16(wb + (uint32_t)(r * LDF + seg * 4) * 4,
                     &W[(long)r * Cc + k0 + seg * 4]);
            }
            CP_COMMIT();
        }

        // MMA on current buffer, converting fragments in registers
        const int r0 = warp * 32;
#pragma unroll
        for (int s = 0; s < 4; s++) {
            const int kk = s * 16 + lc;
            uint32_t ah[2][4], al[2][4];
#pragma unroll
            for (int m = 0; m < 2; m++) {
                int rr = r0 + m * 16 + lr;
                cvt_hilo(*(const float2*)&cur.Xs[rr][kk],     ah[m][0], al[m][0]);
                cvt_hilo(*(const float2*)&cur.Xs[rr + 8][kk], ah[m][1], al[m][1]);
                cvt_hilo(*(const float2*)&cur.Xs[rr][kk + 8], ah[m][2], al[m][2]);
                cvt_hilo(*(const float2*)&cur.Xs[rr + 8][kk + 8], ah[m][3], al[m][3]);
            }
#pragma unroll
            for (int n = 0; n < 8; n++) {
                int wr = n * 8 + lr;
                uint32_t bh0, bl0, bh1, bl1;
                cvt_hilo(*(const float2*)&cur.Ws[wr][kk],     bh0, bl0);
                cvt_hilo(*(const float2*)&cur.Ws[wr][kk + 8], bh1, bl1);
#pragma unroll
                for (int m = 0; m < 2; m++) {
                    mma_bf16(acc[m][n], ah[m][0], ah[m][1], ah[m][2], ah[m][3], bh0, bh1);
                    mma_bf16(acc[m][n], ah[m][0], ah[m][1], ah[m][2], ah[m][3], bl0, bl1);
                    mma_bf16(acc[m][n], al[m][0], al[m][1], al[m][2], al[m][3], bh0, bh1);
                }
            }
        }
        __syncthreads();   // all reads of cur done before it is refilled next+1
    }

#pragma unroll
    for (int m = 0; m < 2; m++) {
        long rr = row0 + warp * 32 + m * 16 + lr;
#pragma unroll
        for (int n = 0; n < 8; n++) {
            int col = n * 8 + lc;
            *(float2*)&out[rr * Hh + col]       = make_float2(acc[m][n][0], acc[m][n][1]);
            *(float2*)&out[(rr + 8) * Hh + col] = make_float2(acc[m][n][2], acc[m][n][3]);
        }
    }
}

// ===========================================================================
// Phase 1: split-KV flash attention (unchanged from R4).
// ===========================================================================
struct ASmem {
    __nv_bfloat16 Qh[64][LDW];
    __nv_bfloat16 Ql[64][LDW];
    __nv_bfloat16 Kh[64][LDW];
    __nv_bfloat16 Kl[64][LDW];
    __nv_bfloat16 Vth[64][LDW];
    __nv_bfloat16 Vtl[64][LDW];
};

__global__ __launch_bounds__(128, 4) void attn_kernel()
{
    extern __shared__ char smraw2[];
    ASmem& sm = *reinterpret_cast<ASmem*>(smraw2);

    const int tid = threadIdx.x;
    const int warp = tid >> 5;
    const int lane = tid & 31;
    const int lr = lane >> 2;
    const int lc = (lane & 3) * 2;
    const int bb = blockIdx.y;

    int rem = blockIdx.x;
    int tq = 0;
#pragma unroll 1
    for (; tq < 64; tq++) {
        int nt = min(tq + 2, 64);
        int nc = (nt + CHUNK - 1) >> 3;
        if (rem < nc) break;
        rem -= nc;
    }
    const int c = rem;
    const int q0 = tq * 64;
    const int ntiles = min(tq + 2, Tt / 64);
    const int tstart = c * CHUNK;
    const int tend = min(tstart + CHUNK, ntiles);

    const float* Qg = g_Q + (long)bb * Tt * Hh;
    const float* Kg = g_K + (long)bb * Tt * Hh;
    const float* Vg = g_V + (long)bb * Tt * Hh;

    for (int i = tid; i < 64 * 32; i += 128) {
        int r = i >> 5, c2 = (i & 31) * 2;
        float2 v = *(const float2*)&Qg[(long)(q0 + r) * Hh + c2];
        __nv_bfloat16 h0 = __float2bfloat16(v.x);
        __nv_bfloat16 h1 = __float2bfloat16(v.y);
        sm.Qh[r][c2] = h0; sm.Qh[r][c2 + 1] = h1;
        sm.Ql[r][c2]     = __float2bfloat16(v.x - __bfloat162float(h0));
        sm.Ql[r][c2 + 1] = __float2bfloat16(v.y - __bfloat162float(h1));
    }

    float m0 = -3.0e38f, m1 = -3.0e38f, l0 = 0.f, l1 = 0.f;
    float oacc[8][4];
#pragma unroll
    for (int n = 0; n < 8; n++)
#pragma unroll
        for (int e = 0; e < 4; e++) oacc[n][e] = 0.f;

    const int qrow = warp * 16 + lr;

    for (int t = tstart; t < tend; t++) {
        const int j0 = t * 64;
        __syncthreads();
        for (int i = tid; i < 64 * 32; i += 128) {
            int r = i >> 5, c2 = (i & 31) * 2;
            float2 v = *(const float2*)&Kg[(long)(j0 + r) * Hh + c2];
            __nv_bfloat16 h0 = __float2bfloat16(v.x);
            __nv_bfloat16 h1 = __float2bfloat16(v.y);
            sm.Kh[r][c2] = h0; sm.Kh[r][c2 + 1] = h1;
            sm.Kl[r][c2]     = __float2bfloat16(v.x - __bfloat162float(h0));
            sm.Kl[r][c2 + 1] = __float2bfloat16(v.y - __bfloat162float(h1));
        }
        for (int i = tid; i < 64 * 64; i += 128) {
            int k = i >> 6, h = i & 63;
            float v = Vg[(long)(j0 + k) * Hh + h];
            __nv_bfloat16 hv = __float2bfloat16(v);
            sm.Vth[h][k] = hv;
            sm.Vtl[h][k] = __float2bfloat16(v - __bfloat162float(hv));
        }
        __syncthreads();

        float sc[8][4];
#pragma unroll
        for (int n = 0; n < 8; n++)
#pragma unroll
            for (int e = 0; e < 4; e++) sc[n][e] = 0.f;
#pragma unroll
        for (int s = 0; s < 4; s++) {
            const int kk = s * 16 + lc;
            uint32_t ah0 = *(const uint32_t*)&sm.Qh[qrow][kk];
            uint32_t ah1 = *(const uint32_t*)&sm.Qh[qrow + 8][kk];
            uint32_t ah2 = *(const uint32_t*)&sm.Qh[qrow][kk + 8];
            uint32_t ah3 = *(const uint32_t*)&sm.Qh[qrow + 8][kk + 8];
            uint32_t al0 = *(const uint32_t*)&sm.Ql[qrow][kk];
            uint32_t al1 = *(const uint32_t*)&sm.Ql[qrow + 8][kk];
            uint32_t al2 = *(const uint32_t*)&sm.Ql[qrow][kk + 8];
            uint32_t al3 = *(const uint32_t*)&sm.Ql[qrow + 8][kk + 8];
#pragma unroll
            for (int n = 0; n < 8; n++) {
                int kr = n * 8 + lr;
                uint32_t bh0 = *(const uint32_t*)&sm.Kh[kr][kk];
                uint32_t bh1 = *(const uint32_t*)&sm.Kh[kr][kk + 8];
                uint32_t bl0 = *(const uint32_t*)&sm.Kl[kr][kk];
                uint32_t bl1 = *(const uint32_t*)&sm.Kl[kr][kk + 8];
                mma_bf16(sc[n], ah0, ah1, ah2, ah3, bh0, bh1);
                mma_bf16(sc[n], ah0, ah1, ah2, ah3, bl0, bl1);
                mma_bf16(sc[n], al0, al1, al2, al3, bh0, bh1);
            }
        }

        if (j0 >= q0) {
            const int i0 = q0 + qrow;
#pragma unroll
            for (int n = 0; n < 8; n++) {
                int j = j0 + n * 8 + lc;
                if (j     > i0 + 1) sc[n][0] = -3.0e38f;
                if (j + 1 > i0 + 1) sc[n][1] = -3.0e38f;
                if (j     > i0 + 9) sc[n][2] = -3.0e38f;
                if (j + 1 > i0 + 9) sc[n][3] = -3.0e38f;
            }
        }

        float rmax0 = -3.0e38f, rmax1 = -3.0e38f;
#pragma unroll
        for (int n = 0; n < 8; n++) {
            rmax0 = fmaxf(rmax0, fmaxf(sc[n][0], sc[n][1]));
            rmax1 = fmaxf(rmax1, fmaxf(sc[n][2], sc[n][3]));
        }
        rmax0 = fmaxf(rmax0, __shfl_xor_sync(0xffffffffu, rmax0, 1));
        rmax0 = fmaxf(rmax0, __shfl_xor_sync(0xffffffffu, rmax0, 2));
        rmax1 = fmaxf(rmax1, __shfl_xor_sync(0xffffffffu, rmax1, 1));
        rmax1 = fmaxf(rmax1, __shfl_xor_sync(0xffffffffu, rmax1, 2));
        float mn0 = fmaxf(m0, rmax0), mn1 = fmaxf(m1, rmax1);
        float alpha0 = exp2f((m0 - mn0) * S2L2E);
        float alpha1 = exp2f((m1 - mn1) * S2L2E);
        m0 = mn0; m1 = mn1;
        const float me0 = fmaxf(mn0, -1.0e30f);
        const float me1 = fmaxf(mn1, -1.0e30f);
        float ps0 = 0.f, ps1 = 0.f;
#pragma unroll
        for (int n = 0; n < 8; n++) {
            sc[n][0] = exp2f((sc[n][0] - me0) * S2L2E);
            sc[n][1] = exp2f((sc[n][1] - me0) * S2L2E);
            sc[n][2] = exp2f((sc[n][2] - me1) * S2L2E);
            sc[n][3] = exp2f((sc[n][3] - me1) * S2L2E);
            ps0 += sc[n][0] + sc[n][1];
            ps1 += sc[n][2] + sc[n][3];
        }
        ps0 += __shfl_xor_sync(0xffffffffu, ps0, 1);
        ps0 += __shfl_xor_sync(0xffffffffu, ps0, 2);
        ps1 += __shfl_xor_sync(0xffffffffu, ps1, 1);
        ps1 += __shfl_xor_sync(0xffffffffu, ps1, 2);
        l0 = l0 * alpha0 + ps0;
        l1 = l1 * alpha1 + ps1;
#pragma unroll
        for (int n = 0; n < 8; n++) {
            oacc[n][0] *= alpha0; oacc[n][1] *= alpha0;
            oacc[n][2] *= alpha1; oacc[n][3] *= alpha1;
        }

#pragma unroll
        for (int s = 0; s < 4; s++) {
            const int t0 = 2 * s, t1 = 2 * s + 1;
            uint32_t ph0 = packbf(sc[t0][0], sc[t0][1]);
            uint32_t ph1 = packbf(sc[t0][2], sc[t0][3]);
            uint32_t ph2 = packbf(sc[t1][0], sc[t1][1]);
            uint32_t ph3 = packbf(sc[t1][2], sc[t1][3]);
            __nv_bfloat162* hp;
            uint32_t pl0, pl1, pl2, pl3;
            hp = (__nv_bfloat162*)&ph0;
            pl0 = packbf(sc[t0][0] - __bfloat162float(hp->x),
                         sc[t0][1] - __bfloat162float(hp->y));
            hp = (__nv_bfloat162*)&ph1;
            pl1 = packbf(sc[t0][2] - __bfloat162float(hp->x),
                         sc[t0][3] - __bfloat162float(hp->y));
            hp = (__nv_bfloat162*)&ph2;
            pl2 = packbf(sc[t1][0] - __bfloat162float(hp->x),
                         sc[t1][1] - __bfloat162float(hp->y));
            hp = (__nv_bfloat162*)&ph3;
            pl3 = packbf(sc[t1][2] - __bfloat162float(hp->x),
                         sc[t1][3] - __bfloat162float(hp->y));
            const int kk = s * 16 + lc;
#pragma unroll
            for (int n = 0; n < 8; n++) {
                int vr = n * 8 + lr;
                uint32_t bh0 = *(const uint32_t*)&sm.Vth[vr][kk];
                uint32_t bh1 = *(const uint32_t*)&sm.Vth[vr][kk + 8];
                uint32_t bl0 = *(const uint32_t*)&sm.Vtl[vr][kk];
                uint32_t bl1 = *(const uint32_t*)&sm.Vtl[vr][kk + 8];
                mma_bf16(oacc[n], ph0, ph1, ph2, ph3, bh0, bh1);
                mma_bf16(oacc[n], ph0, ph1, ph2, ph3, bl0, bl1);
                mma_bf16(oacc[n], pl0, pl1, pl2, pl3, bh0, bh1);
            }
        }
    }

    const long pbase = (((long)bb * 64 + tq) * MAXC + c) * 64;
    float* Op = g_Opart + pbase * 64;
#pragma unroll
    for (int n = 0; n < 8; n++) {
        int col = n * 8 + lc;
        *(float2*)&Op[(long)qrow * 64 + col] = make_float2(oacc[n][0], oacc[n][1]);
        *(float2*)&Op[(long)(qrow + 8) * 64 + col] = make_float2(oacc[n][2], oacc[n][3]);
    }
    if ((lane & 3) == 0) {
        g_Mpart[pbase + qrow] = m0;
        g_Mpart[pbase + qrow + 8] = m1;
        g_Lpart[pbase + qrow] = l0;
        g_Lpart[pbase + qrow + 8] = l1;
    }
}

// ===========================================================================
// Phase 2: merge partials (unchanged from R4).
// ===========================================================================
__global__ __launch_bounds__(256) void merge_kernel(float* __restrict__ out)
{
    const int tid = threadIdx.x;
    const int r = tid >> 2;
    const int cg = (tid & 3) * 16;
    const int tq = blockIdx.x;
    const int bb = blockIdx.y;

    const int ntiles = min(tq + 2, Tt / 64);
    const int nc = (ntiles + CHUNK - 1) >> 3;
    const long base = ((long)bb * 64 + tq) * MAXC;

    float M = -3.0e38f;
    for (int c = 0; c < nc; c++)
        M = fmaxf(M, g_Mpart[(base + c) * 64 + r]);

    float acc[16];
#pragma unroll
    for (int i = 0; i < 16; i++) acc[i] = 0.f;
    float ltot = 0.f;

    for (int c = 0; c < nc; c++) {
        float mc = g_Mpart[(base + c) * 64 + r];
        float w = exp2f((mc - M) * S2L2E);
        ltot += w * g_Lpart[(base + c) * 64 + r];
        const float* Op = g_Opart + ((base + c) * 64 + r) * 64 + cg;
#pragma unroll
        for (int i = 0; i < 4; i++) {
            float4 v = *(const float4*)&Op[i * 4];
            acc[i * 4 + 0] += w * v.x;
            acc[i * 4 + 1] += w * v.y;
            acc[i * 4 + 2] += w * v.z;
            acc[i * 4 + 3] += w * v.w;
        }
    }

    const float inv = 1.0f / ltot;
    float* orow = out + ((long)bb * Tt + tq * 64 + r) * Hh + cg;
#pragma unroll
    for (int i = 0; i < 4; i++) {
        float4 o;
        o.x = acc[i * 4 + 0] * inv;
        o.y = acc[i * 4 + 1] * inv;
        o.z = acc[i * 4 + 2] * inv;
        o.w = acc[i * 4 + 3] * inv;
        *(float4*)&orow[i * 4] = o;
    }
}

// ===========================================================================
extern "C" void kernel_launch(void* const* d_in, const int* in_sizes, int n_in,
                              void* d_out, int out_size)
{
    const float* q  = (const float*)d_in[0];
    const float* k  = (const float*)d_in[1];
    const float* v  = (const float*)d_in[2];
    const float* Wq = (const float*)d_in[3];
    const float* Wk = (const float*)d_in[4];
    const float* Wv = (const float*)d_in[5];
    float* out = (float*)d_out;

    cudaFuncSetAttribute(proj_kernel,
                         cudaFuncAttributeMaxDynamicSharedMemorySize,
                         (int)(2 * sizeof(PBuf)));
    cudaFuncSetAttribute(attn_kernel,
                         cudaFuncAttributeMaxDynamicSharedMemorySize,
                         (int)sizeof(ASmem));

    dim3 pgrid((Bb * Tt) / 128, 1, 3);
    proj_kernel<<<pgrid, 128, 2 * sizeof(PBuf)>>>(q, k, v, Wq, Wk, Wv);
    attn_kernel<<<dim3(NCHUNKS, Bb), 128, sizeof(ASmem)>>>();
    merge_kernel<<<dim3(Tt / 64, Bb), 256>>>(out);
}

// round 9
// speedup vs baseline: 3.5773x; 1.0289x over previous
#include <cuda_runtime.h>
#include <cuda_bf16.h>
#include <cstdint>

#define Bb 4
#define Tt 4096
#define Cc 1024
#define Hh 64

// combined scale: softmax(QK^T /64); exp(x/64) = exp2(x * log2e/64)
#define S2L2E 0.022542110f

#define CHUNK 8
#define MAXC 8
#define NCHUNKS 295

__device__ float g_Q[Bb * Tt * Hh];
__device__ float g_K[Bb * Tt * Hh];
__device__ float g_V[Bb * Tt * Hh];

__device__ float g_Opart[Bb * 64 * MAXC * 64 * 64];
__device__ float g_Mpart[Bb * 64 * MAXC * 64];
__device__ float g_Lpart[Bb * 64 * MAXC * 64];

// ---------------------------------------------------------------------------
__device__ __forceinline__ void mma_bf16(float c[4], uint32_t a0, uint32_t a1,
                                         uint32_t a2, uint32_t a3,
                                         uint32_t b0, uint32_t b1) {
    asm volatile(
        "mma.sync.aligned.m16n8k16.row.col.f32.bf16.bf16.f32 "
        "{%0,%1,%2,%3}, {%4,%5,%6,%7}, {%8,%9}, {%0,%1,%2,%3};"
        : "+f"(c[0]), "+f"(c[1]), "+f"(c[2]), "+f"(c[3])
        : "r"(a0), "r"(a1), "r"(a2), "r"(a3), "r"(b0), "r"(b1));
}

__device__ __forceinline__ uint32_t packbf(float a, float b) {
    __nv_bfloat162 t;
    t.x = __float2bfloat16(a);
    t.y = __float2bfloat16(b);
    return *reinterpret_cast<uint32_t*>(&t);
}

// fp32 pair -> packed bf16 hi and packed bf16 lo (residual)
__device__ __forceinline__ void cvt_hilo(float2 v, uint32_t& hi, uint32_t& lo) {
    asm("cvt.rn.bf16x2.f32 %0, %1, %2;" : "=r"(hi) : "f"(v.y), "f"(v.x));
    __nv_bfloat162 h = *reinterpret_cast<__nv_bfloat162*>(&hi);
    float lx = v.x - __bfloat162float(h.x);
    float ly = v.y - __bfloat162float(h.y);
    asm("cvt.rn.bf16x2.f32 %0, %1, %2;" : "=r"(lo) : "f"(ly), "f"(lx));
}

__device__ __forceinline__ void cp16(uint32_t saddr, const void* gaddr) {
    asm volatile("cp.async.cg.shared.global [%0], [%1], 16;"
                 :: "r"(saddr), "l"(gaddr) : "memory");
}
#define CP_COMMIT() asm volatile("cp.async.commit_group;" ::: "memory")
#define CP_WAIT0()  asm volatile("cp.async.wait_group 0;" ::: "memory")

__device__ __forceinline__ uint32_t smem_u32(const void* p) {
    uint32_t a;
    asm("{ .reg .u64 t; cvta.to.shared.u64 t, %1; cvt.u32.u64 %0, t; }"
        : "=r"(a) : "l"(p));
    return a;
}

#define LDF 72  // fp32 row stride (288B); 72 mod 32 = 8 -> conflict-free frag LDS

// ===========================================================================
// Projection (unchanged from R7): cp.async double-buffer + in-register bf16x3.
// ===========================================================================
struct PBuf {
    float Xs[128][LDF];
    float Ws[64][LDF];
};

__global__ __launch_bounds__(128, 2) void proj_kernel(
    const float* __restrict__ xq, const float* __restrict__ xk,
    const float* __restrict__ xv,
    const float* __restrict__ Wq, const float* __restrict__ Wk,
    const float* __restrict__ Wv)
{
    extern __shared__ char smraw[];
    PBuf* buf = reinterpret_cast<PBuf*>(smraw);

    const float* x;
    const float* W;
    float* out;
    if (blockIdx.z == 0)      { x = xq; W = Wq; out = g_Q; }
    else if (blockIdx.z == 1) { x = xk; W = Wk; out = g_K; }
    else                      { x = xv; W = Wv; out = g_V; }

    const int tid = threadIdx.x;
    const int warp = tid >> 5;
    const int lane = tid & 31;
    const int lr = lane >> 2;
    const int lc = (lane & 3) * 2;
    const long row0 = (long)blockIdx.x * 128;

    float acc[2][8][4];
#pragma unroll
    for (int m = 0; m < 2; m++)
#pragma unroll
        for (int n = 0; n < 8; n++)
#pragma unroll
            for (int e = 0; e < 4; e++) acc[m][n][e] = 0.f;

    {
        const uint32_t xb = smem_u32(&buf[0].Xs[0][0]);
        const uint32_t wb = smem_u32(&buf[0].Ws[0][0]);
#pragma unroll
        for (int i = 0; i < 16; i++) {
            int idx = tid + i * 128;
            int r = idx >> 4, seg = idx & 15;
            cp16(xb + (uint32_t)(r * LDF + seg * 4) * 4,
                 &x[(row0 + r) * Cc + 0 + seg * 4]);
        }
#pragma unroll
        for (int i = 0; i < 8; i++) {
            int idx = tid + i * 128;
            int r = idx >> 4, seg = idx & 15;
            cp16(wb + (uint32_t)(r * LDF + seg * 4) * 4,
                 &W[(long)r * Cc + 0 + seg * 4]);
        }
        CP_COMMIT();
    }

    for (int chunk = 0; chunk < 16; chunk++) {
        const PBuf& cur = buf[chunk & 1];
        CP_WAIT0();
        __syncthreads();

        if (chunk < 15) {
            const int k0 = (chunk + 1) * 64;
            PBuf& nxt = buf[(chunk + 1) & 1];
            const uint32_t xb = smem_u32(&nxt.Xs[0][0]);
            const uint32_t wb = smem_u32(&nxt.Ws[0][0]);
#pragma unroll
            for (int i = 0; i < 16; i++) {
                int idx = tid + i * 128;
                int r = idx >> 4, seg = idx & 15;
                cp16(xb + (uint32_t)(r * LDF + seg * 4) * 4,
                     &x[(row0 + r) * Cc + k0 + seg * 4]);
            }
#pragma unroll
            for (int i = 0; i < 8; i++) {
                int idx = tid + i * 128;
                int r = idx >> 4, seg = idx & 15;
                cp16(wb + (uint32_t)(r * LDF + seg * 4) * 4,
                     &W[(long)r * Cc + k0 + seg * 4]);
            }
            CP_COMMIT();
        }

        const int r0 = warp * 32;
#pragma unroll
        for (int s = 0; s < 4; s++) {
            const int kk = s * 16 + lc;
            uint32_t ah[2][4], al[2][4];
#pragma unroll
            for (int m = 0; m < 2; m++) {
                int rr = r0 + m * 16 + lr;
                cvt_hilo(*(const float2*)&cur.Xs[rr][kk],     ah[m][0], al[m][0]);
                cvt_hilo(*(const float2*)&cur.Xs[rr + 8][kk], ah[m][1], al[m][1]);
                cvt_hilo(*(const float2*)&cur.Xs[rr][kk + 8], ah[m][2], al[m][2]);
                cvt_hilo(*(const float2*)&cur.Xs[rr + 8][kk + 8], ah[m][3], al[m][3]);
            }
#pragma unroll
            for (int n = 0; n < 8; n++) {
                int wr = n * 8 + lr;
                uint32_t bh0, bl0, bh1, bl1;
                cvt_hilo(*(const float2*)&cur.Ws[wr][kk],     bh0, bl0);
                cvt_hilo(*(const float2*)&cur.Ws[wr][kk + 8], bh1, bl1);
#pragma unroll
                for (int m = 0; m < 2; m++) {
                    mma_bf16(acc[m][n], ah[m][0], ah[m][1], ah[m][2], ah[m][3], bh0, bh1);
                    mma_bf16(acc[m][n], ah[m][0], ah[m][1], ah[m][2], ah[m][3], bl0, bl1);
                    mma_bf16(acc[m][n], al[m][0], al[m][1], al[m][2], al[m][3], bh0, bh1);
                }
            }
        }
        __syncthreads();
    }

#pragma unroll
    for (int m = 0; m < 2; m++) {
        long rr = row0 + warp * 32 + m * 16 + lr;
#pragma unroll
        for (int n = 0; n < 8; n++) {
            int col = n * 8 + lc;
            *(float2*)&out[rr * Hh + col]       = make_float2(acc[m][n][0], acc[m][n][1]);
            *(float2*)&out[(rr + 8) * Hh + col] = make_float2(acc[m][n][2], acc[m][n][3]);
        }
    }
}

// ===========================================================================
// Phase 1: split-KV flash attention, cp.async double-buffered fp32 K/V tiles,
// fragment-time bf16x3 conversion, V kept row-major (no transpose staging).
// ===========================================================================
struct ABuf {
    float Ks[64][LDF];   // [kv][h]
    float Vs[64][LDF];   // [kv][h]
};
struct ASmem {
    float Qs[64][LDF];
    ABuf buf[2];
};                       // 18432 + 2*36864 = 92160 B

__global__ __launch_bounds__(128) void attn_kernel()
{
    extern __shared__ char smraw2[];
    ASmem& sm = *reinterpret_cast<ASmem*>(smraw2);

    const int tid = threadIdx.x;
    const int warp = tid >> 5;
    const int lane = tid & 31;
    const int lr = lane >> 2;
    const int lc = (lane & 3) * 2;
    const int bb = blockIdx.y;

    int rem = blockIdx.x;
    int tq = 0;
#pragma unroll 1
    for (; tq < 64; tq++) {
        int nt = min(tq + 2, 64);
        int nc = (nt + CHUNK - 1) >> 3;
        if (rem < nc) break;
        rem -= nc;
    }
    const int c = rem;
    const int q0 = tq * 64;
    const int ntiles = min(tq + 2, Tt / 64);
    const int tstart = c * CHUNK;
    const int tend = min(tstart + CHUNK, ntiles);

    const float* Qg = g_Q + (long)bb * Tt * Hh;
    const float* Kg = g_K + (long)bb * Tt * Hh;
    const float* Vg = g_V + (long)bb * Tt * Hh;

    // issue Q + first K/V tile loads
    {
        const uint32_t qb = smem_u32(&sm.Qs[0][0]);
        const uint32_t kb = smem_u32(&sm.buf[0].Ks[0][0]);
        const uint32_t vb = smem_u32(&sm.buf[0].Vs[0][0]);
        const int j0 = tstart * 64;
#pragma unroll
        for (int i = 0; i < 8; i++) {       // 1024 16B segs each / 128 thr
            int idx = tid + i * 128;
            int r = idx >> 4, seg = idx & 15;
            uint32_t soff = (uint32_t)(r * LDF + seg * 4) * 4;
            cp16(qb + soff, &Qg[(long)(q0 + r) * Hh + seg * 4]);
            cp16(kb + soff, &Kg[(long)(j0 + r) * Hh + seg * 4]);
            cp16(vb + soff, &Vg[(long)(j0 + r) * Hh + seg * 4]);
        }
        CP_COMMIT();
    }

    float m0 = -3.0e38f, m1 = -3.0e38f, l0 = 0.f, l1 = 0.f;
    float oacc[8][4];
#pragma unroll
    for (int n = 0; n < 8; n++)
#pragma unroll
        for (int e = 0; e < 4; e++) oacc[n][e] = 0.f;

    const int qrow = warp * 16 + lr;

    for (int t = tstart; t < tend; t++) {
        const int j0 = t * 64;
        const ABuf& cur = sm.buf[(t - tstart) & 1];
        CP_WAIT0();
        __syncthreads();   // cur data visible; prior reads of the other buf done

        if (t + 1 < tend) {
            const int j1 = (t + 1) * 64;
            ABuf& nxt = sm.buf[(t + 1 - tstart) & 1];
            const uint32_t kb = smem_u32(&nxt.Ks[0][0]);
            const uint32_t vb = smem_u32(&nxt.Vs[0][0]);
#pragma unroll
            for (int i = 0; i < 8; i++) {
                int idx = tid + i * 128;
                int r = idx >> 4, seg = idx & 15;
                uint32_t soff = (uint32_t)(r * LDF + seg * 4) * 4;
                cp16(kb + soff, &Kg[(long)(j1 + r) * Hh + seg * 4]);
                cp16(vb + soff, &Vg[(long)(j1 + r) * Hh + seg * 4]);
            }
            CP_COMMIT();
        }

        // ---- S = Q K^T (bf16x3, fragment-time conversion) ----
        float sc[8][4];
#pragma unroll
        for (int n = 0; n < 8; n++)
#pragma unroll
            for (int e = 0; e < 4; e++) sc[n][e] = 0.f;
#pragma unroll
        for (int s = 0; s < 4; s++) {
            const int kk = s * 16 + lc;
            uint32_t ah0, ah1, ah2, ah3, al0, al1, al2, al3;
            cvt_hilo(*(const float2*)&sm.Qs[qrow][kk],         ah0, al0);
            cvt_hilo(*(const float2*)&sm.Qs[qrow + 8][kk],     ah1, al1);
            cvt_hilo(*(const float2*)&sm.Qs[qrow][kk + 8],     ah2, al2);
            cvt_hilo(*(const float2*)&sm.Qs[qrow + 8][kk + 8], ah3, al3);
#pragma unroll
            for (int n = 0; n < 8; n++) {
                int kr = n * 8 + lr;
                uint32_t bh0, bl0, bh1, bl1;
                cvt_hilo(*(const float2*)&cur.Ks[kr][kk],     bh0, bl0);
                cvt_hilo(*(const float2*)&cur.Ks[kr][kk + 8], bh1, bl1);
                mma_bf16(sc[n], ah0, ah1, ah2, ah3, bh0, bh1);
                mma_bf16(sc[n], ah0, ah1, ah2, ah3, bl0, bl1);
                mma_bf16(sc[n], al0, al1, al2, al3, bh0, bh1);
            }
        }

        // ---- causal mask (diag offset +1) ----
        if (j0 >= q0) {
            const int i0 = q0 + qrow;
#pragma unroll
            for (int n = 0; n < 8; n++) {
                int j = j0 + n * 8 + lc;
                if (j     > i0 + 1) sc[n][0] = -3.0e38f;
                if (j + 1 > i0 + 1) sc[n][1] = -3.0e38f;
                if (j     > i0 + 9) sc[n][2] = -3.0e38f;
                if (j + 1 > i0 + 9) sc[n][3] = -3.0e38f;
            }
        }

        // ---- register online softmax ----
        float rmax0 = -3.0e38f, rmax1 = -3.0e38f;
#pragma unroll
        for (int n = 0; n < 8; n++) {
            rmax0 = fmaxf(rmax0, fmaxf(sc[n][0], sc[n][1]));
            rmax1 = fmaxf(rmax1, fmaxf(sc[n][2], sc[n][3]));
        }
        rmax0 = fmaxf(rmax0, __shfl_xor_sync(0xffffffffu, rmax0, 1));
        rmax0 = fmaxf(rmax0, __shfl_xor_sync(0xffffffffu, rmax0, 2));
        rmax1 = fmaxf(rmax1, __shfl_xor_sync(0xffffffffu, rmax1, 1));
        rmax1 = fmaxf(rmax1, __shfl_xor_sync(0xffffffffu, rmax1, 2));
        float mn0 = fmaxf(m0, rmax0), mn1 = fmaxf(m1, rmax1);
        float alpha0 = exp2f((m0 - mn0) * S2L2E);
        float alpha1 = exp2f((m1 - mn1) * S2L2E);
        m0 = mn0; m1 = mn1;
        const float me0 = fmaxf(mn0, -1.0e30f);
        const float me1 = fmaxf(mn1, -1.0e30f);
        float ps0 = 0.f, ps1 = 0.f;
#pragma unroll
        for (int n = 0; n < 8; n++) {
            sc[n][0] = exp2f((sc[n][0] - me0) * S2L2E);
            sc[n][1] = exp2f((sc[n][1] - me0) * S2L2E);
            sc[n][2] = exp2f((sc[n][2] - me1) * S2L2E);
            sc[n][3] = exp2f((sc[n][3] - me1) * S2L2E);
            ps0 += sc[n][0] + sc[n][1];
            ps1 += sc[n][2] + sc[n][3];
        }
        ps0 += __shfl_xor_sync(0xffffffffu, ps0, 1);
        ps0 += __shfl_xor_sync(0xffffffffu, ps0, 2);
        ps1 += __shfl_xor_sync(0xffffffffu, ps1, 1);
        ps1 += __shfl_xor_sync(0xffffffffu, ps1, 2);
        l0 = l0 * alpha0 + ps0;
        l1 = l1 * alpha1 + ps1;
#pragma unroll
        for (int n = 0; n < 8; n++) {
            oacc[n][0] *= alpha0; oacc[n][1] *= alpha0;
            oacc[n][2] *= alpha1; oacc[n][3] *= alpha1;
        }

        // ---- O += P V (bf16x3); P in registers, V row-major fragment loads ----
#pragma unroll
        for (int s = 0; s < 4; s++) {
            const int t0 = 2 * s, t1 = 2 * s + 1;
            uint32_t ph0 = packbf(sc[t0][0], sc[t0][1]);
            uint32_t ph1 = packbf(sc[t0][2], sc[t0][3]);
            uint32_t ph2 = packbf(sc[t1][0], sc[t1][1]);
            uint32_t ph3 = packbf(sc[t1][2], sc[t1][3]);
            __nv_bfloat162* hp;
            uint32_t pl0, pl1, pl2, pl3;
            hp = (__nv_bfloat162*)&ph0;
            pl0 = packbf(sc[t0][0] - __bfloat162float(hp->x),
                         sc[t0][1] - __bfloat162float(hp->y));
            hp = (__nv_bfloat162*)&ph1;
            pl1 = packbf(sc[t0][2] - __bfloat162float(hp->x),
                         sc[t0][3] - __bfloat162float(hp->y));
            hp = (__nv_bfloat162*)&ph2;
            pl2 = packbf(sc[t1][0] - __bfloat162float(hp->x),
                         sc[t1][1] - __bfloat162float(hp->y));
            hp = (__nv_bfloat162*)&ph3;
            pl3 = packbf(sc[t1][2] - __bfloat162float(hp->x),
                         sc[t1][3] - __bfloat162float(hp->y));
            const int kk = s * 16 + lc;   // kv index base for this k-step
#pragma unroll
            for (int n = 0; n < 8; n++) {
                int vr = n * 8 + lr;      // h column
                uint32_t bh0, bl0, bh1, bl1;
                cvt_hilo(make_float2(cur.Vs[kk][vr], cur.Vs[kk + 1][vr]), bh0, bl0);
                cvt_hilo(make_float2(cur.Vs[kk + 8][vr], cur.Vs[kk + 9][vr]), bh1, bl1);
                mma_bf16(oacc[n], ph0, ph1, ph2, ph3, bh0, bh1);
                mma_bf16(oacc[n], ph0, ph1, ph2, ph3, bl0, bl1);
                mma_bf16(oacc[n], pl0, pl1, pl2, pl3, bh0, bh1);
            }
        }
        __syncthreads();   // all reads of cur done before its refill (t+2)
    }

    const long pbase = (((long)bb * 64 + tq) * MAXC + c) * 64;
    float* Op = g_Opart + pbase * 64;
#pragma unroll
    for (int n = 0; n < 8; n++) {
        int col = n * 8 + lc;
        *(float2*)&Op[(long)qrow * 64 + col] = make_float2(oacc[n][0], oacc[n][1]);
        *(float2*)&Op[(long)(qrow + 8) * 64 + col] = make_float2(oacc[n][2], oacc[n][3]);
    }
    if ((lane & 3) == 0) {
        g_Mpart[pbase + qrow] = m0;
        g_Mpart[pbase + qrow + 8] = m1;
        g_Lpart[pbase + qrow] = l0;
        g_Lpart[pbase + qrow + 8] = l1;
    }
}

// ===========================================================================
// Phase 2: merge partials (unchanged).
// ===========================================================================
__global__ __launch_bounds__(256) void merge_kernel(float* __restrict__ out)
{
    const int tid = threadIdx.x;
    const int r = tid >> 2;
    const int cg = (tid & 3) * 16;
    const int tq = blockIdx.x;
    const int bb = blockIdx.y;

    const int ntiles = min(tq + 2, Tt / 64);
    const int nc = (ntiles + CHUNK - 1) >> 3;
    const long base = ((long)bb * 64 + tq) * MAXC;

    float M = -3.0e38f;
    for (int c = 0; c < nc; c++)
        M = fmaxf(M, g_Mpart[(base + c) * 64 + r]);

    float acc[16];
#pragma unroll
    for (int i = 0; i < 16; i++) acc[i] = 0.f;
    float ltot = 0.f;

    for (int c = 0; c < nc; c++) {
        float mc = g_Mpart[(base + c) * 64 + r];
        float w = exp2f((mc - M) * S2L2E);
        ltot += w * g_Lpart[(base + c) * 64 + r];
        const float* Op = g_Opart + ((base + c) * 64 + r) * 64 + cg;
#pragma unroll
        for (int i = 0; i < 4; i++) {
            float4 v = *(const float4*)&Op[i * 4];
            acc[i * 4 + 0] += w * v.x;
            acc[i * 4 + 1] += w * v.y;
            acc[i * 4 + 2] += w * v.z;
            acc[i * 4 + 3] += w * v.w;
        }
    }

    const float inv = 1.0f / ltot;
    float* orow = out + ((long)bb * Tt + tq * 64 + r) * Hh + cg;
#pragma unroll
    for (int i = 0; i < 4; i++) {
        float4 o;
        o.x = acc[i * 4 + 0] * inv;
        o.y = acc[i * 4 + 1] * inv;
        o.z = acc[i * 4 + 2] * inv;
        o.w = acc[i * 4 + 3] * inv;
        *(float4*)&orow[i * 4] = o;
    }
}

// ===========================================================================
extern "C" void kernel_launch(void* const* d_in, const int* in_sizes, int n_in,
                              void* d_out, int out_size)
{
    const float* q  = (const float*)d_in[0];
    const float* k  = (const float*)d_in[1];
    const float* v  = (const float*)d_in[2];
    const float* Wq = (const float*)d_in[3];
    const float* Wk = (const float*)d_in[4];
    const float* Wv = (const float*)d_in[5];
    float* out = (float*)d_out;

    cudaFuncSetAttribute(proj_kernel,
                         cudaFuncAttributeMaxDynamicSharedMemorySize,
                         (int)(2 * sizeof(PBuf)));
    cudaFuncSetAttribute(attn_kernel,
                         cudaFuncAttributeMaxDynamicSharedMemorySize,
                         (int)sizeof(ASmem));

    dim3 pgrid((Bb * Tt) / 128, 1, 3);
    proj_kernel<<<pgrid, 128, 2 * sizeof(PBuf)>>>(q, k, v, Wq, Wk, Wv);
    attn_kernel<<<dim3(NCHUNKS, Bb), 128, sizeof(ASmem)>>>();
    merge_kernel<<<dim3(Tt / 64, Bb), 256>>>(out);
}

// round 10
// speedup vs baseline: 4.0120x; 1.1215x over previous
#include <cuda_runtime.h>
#include <cuda_bf16.h>
#include <cstdint>

#define Bb 4
#define Tt 4096
#define Cc 1024
#define Hh 64

// combined scale: softmax(QK^T /64); exp(x/64) = exp2(x * log2e/64)
#define S2L2E 0.022542110f

#define CHUNK 8
#define MAXC 8
#define NCHUNKS 295

// packed bf16x2 (h-pairs) hi/lo images of Q,K,V: [B*T][32] words
__device__ uint32_t g_Qh[Bb * Tt * 32];
__device__ uint32_t g_Ql[Bb * Tt * 32];
__device__ uint32_t g_Kh[Bb * Tt * 32];
__device__ uint32_t g_Kl[Bb * Tt * 32];
__device__ uint32_t g_Vh[Bb * Tt * 32];
__device__ uint32_t g_Vl[Bb * Tt * 32];

__device__ float g_Opart[Bb * 64 * MAXC * 64 * 64];
__device__ float g_Mpart[Bb * 64 * MAXC * 64];
__device__ float g_Lpart[Bb * 64 * MAXC * 64];

// ---------------------------------------------------------------------------
__device__ __forceinline__ void mma_bf16(float c[4], uint32_t a0, uint32_t a1,
                                         uint32_t a2, uint32_t a3,
                                         uint32_t b0, uint32_t b1) {
    asm volatile(
        "mma.sync.aligned.m16n8k16.row.col.f32.bf16.bf16.f32 "
        "{%0,%1,%2,%3}, {%4,%5,%6,%7}, {%8,%9}, {%0,%1,%2,%3};"
        : "+f"(c[0]), "+f"(c[1]), "+f"(c[2]), "+f"(c[3])
        : "r"(a0), "r"(a1), "r"(a2), "r"(a3), "r"(b0), "r"(b1));
}

__device__ __forceinline__ void ldmatrix_x4_trans(uint32_t& r0, uint32_t& r1,
                                                  uint32_t& r2, uint32_t& r3,
                                                  uint32_t addr) {
    asm volatile(
        "ldmatrix.sync.aligned.m8n8.x4.trans.shared.b16 {%0,%1,%2,%3}, [%4];"
        : "=r"(r0), "=r"(r1), "=r"(r2), "=r"(r3) : "r"(addr));
}

__device__ __forceinline__ uint32_t packbf(float a, float b) {
    __nv_bfloat162 t;
    t.x = __float2bfloat16(a);
    t.y = __float2bfloat16(b);
    return *reinterpret_cast<uint32_t*>(&t);
}

// fp32 pair -> packed bf16 hi and packed bf16 lo (residual)
__device__ __forceinline__ void cvt_hilo(float2 v, uint32_t& hi, uint32_t& lo) {
    asm("cvt.rn.bf16x2.f32 %0, %1, %2;" : "=r"(hi) : "f"(v.y), "f"(v.x));
    __nv_bfloat162 h = *reinterpret_cast<__nv_bfloat162*>(&hi);
    float lx = v.x - __bfloat162float(h.x);
    float ly = v.y - __bfloat162float(h.y);
    asm("cvt.rn.bf16x2.f32 %0, %1, %2;" : "=r"(lo) : "f"(ly), "f"(lx));
}

__device__ __forceinline__ void cp16(uint32_t saddr, const void* gaddr) {
    asm volatile("cp.async.cg.shared.global [%0], [%1], 16;"
                 :: "r"(saddr), "l"(gaddr) : "memory");
}
#define CP_COMMIT() asm volatile("cp.async.commit_group;" ::: "memory")
#define CP_WAIT0()  asm volatile("cp.async.wait_group 0;" ::: "memory")

__device__ __forceinline__ uint32_t smem_u32(const void* p) {
    uint32_t a;
    asm("{ .reg .u64 t; cvta.to.shared.u64 t, %1; cvt.u32.u64 %0, t; }"
        : "=r"(a) : "l"(p));
    return a;
}

#define LDF 72   // fp32 row stride for proj smem
#define LWW 36   // uint32 (bf16x2) row stride for attn smem (=144B)

// ===========================================================================
// Projection: cp.async double-buffer + in-register bf16x3 (R7 core);
// epilogue writes packed bf16 hi/lo images instead of fp32.
// ===========================================================================
struct PBuf {
    float Xs[128][LDF];
    float Ws[64][LDF];
};

__global__ __launch_bounds__(128, 2) void proj_kernel(
    const float* __restrict__ xq, const float* __restrict__ xk,
    const float* __restrict__ xv,
    const float* __restrict__ Wq, const float* __restrict__ Wk,
    const float* __restrict__ Wv)
{
    extern __shared__ char smraw[];
    PBuf* buf = reinterpret_cast<PBuf*>(smraw);

    const float* x;
    const float* W;
    uint32_t* outh;
    uint32_t* outl;
    if (blockIdx.z == 0)      { x = xq; W = Wq; outh = g_Qh; outl = g_Ql; }
    else if (blockIdx.z == 1) { x = xk; W = Wk; outh = g_Kh; outl = g_Kl; }
    else                      { x = xv; W = Wv; outh = g_Vh; outl = g_Vl; }

    const int tid = threadIdx.x;
    const int warp = tid >> 5;
    const int lane = tid & 31;
    const int lr = lane >> 2;
    const int lc = (lane & 3) * 2;
    const long row0 = (long)blockIdx.x * 128;

    float acc[2][8][4];
#pragma unroll
    for (int m = 0; m < 2; m++)
#pragma unroll
        for (int n = 0; n < 8; n++)
#pragma unroll
            for (int e = 0; e < 4; e++) acc[m][n][e] = 0.f;

    {
        const uint32_t xb = smem_u32(&buf[0].Xs[0][0]);
        const uint32_t wb = smem_u32(&buf[0].Ws[0][0]);
#pragma unroll
        for (int i = 0; i < 16; i++) {
            int idx = tid + i * 128;
            int r = idx >> 4, seg = idx & 15;
            cp16(xb + (uint32_t)(r * LDF + seg * 4) * 4,
                 &x[(row0 + r) * Cc + 0 + seg * 4]);
        }
#pragma unroll
        for (int i = 0; i < 8; i++) {
            int idx = tid + i * 128;
            int r = idx >> 4, seg = idx & 15;
            cp16(wb + (uint32_t)(r * LDF + seg * 4) * 4,
                 &W[(long)r * Cc + 0 + seg * 4]);
        }
        CP_COMMIT();
    }

    for (int chunk = 0; chunk < 16; chunk++) {
        const PBuf& cur = buf[chunk & 1];
        CP_WAIT0();
        __syncthreads();

        if (chunk < 15) {
            const int k0 = (chunk + 1) * 64;
            PBuf& nxt = buf[(chunk + 1) & 1];
            const uint32_t xb = smem_u32(&nxt.Xs[0][0]);
            const uint32_t wb = smem_u32(&nxt.Ws[0][0]);
#pragma unroll
            for (int i = 0; i < 16; i++) {
                int idx = tid + i * 128;
                int r = idx >> 4, seg = idx & 15;
                cp16(xb + (uint32_t)(r * LDF + seg * 4) * 4,
                     &x[(row0 + r) * Cc + k0 + seg * 4]);
            }
#pragma unroll
            for (int i = 0; i < 8; i++) {
                int idx = tid + i * 128;
                int r = idx >> 4, seg = idx & 15;
                cp16(wb + (uint32_t)(r * LDF + seg * 4) * 4,
                     &W[(long)r * Cc + k0 + seg * 4]);
            }
            CP_COMMIT();
        }

        const int r0 = warp * 32;
#pragma unroll
        for (int s = 0; s < 4; s++) {
            const int kk = s * 16 + lc;
            uint32_t ah[2][4], al[2][4];
#pragma unroll
            for (int m = 0; m < 2; m++) {
                int rr = r0 + m * 16 + lr;
                cvt_hilo(*(const float2*)&cur.Xs[rr][kk],     ah[m][0], al[m][0]);
                cvt_hilo(*(const float2*)&cur.Xs[rr + 8][kk], ah[m][1], al[m][1]);
                cvt_hilo(*(const float2*)&cur.Xs[rr][kk + 8], ah[m][2], al[m][2]);
                cvt_hilo(*(const float2*)&cur.Xs[rr + 8][kk + 8], ah[m][3], al[m][3]);
            }
#pragma unroll
            for (int n = 0; n < 8; n++) {
                int wr = n * 8 + lr;
                uint32_t bh0, bl0, bh1, bl1;
                cvt_hilo(*(const float2*)&cur.Ws[wr][kk],     bh0, bl0);
                cvt_hilo(*(const float2*)&cur.Ws[wr][kk + 8], bh1, bl1);
#pragma unroll
                for (int m = 0; m < 2; m++) {
                    mma_bf16(acc[m][n], ah[m][0], ah[m][1], ah[m][2], ah[m][3], bh0, bh1);
                    mma_bf16(acc[m][n], ah[m][0], ah[m][1], ah[m][2], ah[m][3], bl0, bl1);
                    mma_bf16(acc[m][n], al[m][0], al[m][1], al[m][2], al[m][3], bh0, bh1);
                }
            }
        }
        __syncthreads();
    }

    // epilogue: write packed bf16 hi/lo (identical rounding to old attn staging)
#pragma unroll
    for (int m = 0; m < 2; m++) {
        long rr = row0 + warp * 32 + m * 16 + lr;
#pragma unroll
        for (int n = 0; n < 8; n++) {
            int wcol = 4 * n + (lane & 3);
            uint32_t h0, l0, h1, l1;
            cvt_hilo(make_float2(acc[m][n][0], acc[m][n][1]), h0, l0);
            cvt_hilo(make_float2(acc[m][n][2], acc[m][n][3]), h1, l1);
            outh[rr * 32 + wcol] = h0;
            outl[rr * 32 + wcol] = l0;
            outh[(rr + 8) * 32 + wcol] = h1;
            outl[(rr + 8) * 32 + wcol] = l1;
        }
    }
}

// ===========================================================================
// Phase 1: split-KV flash attention. Pre-converted bf16 hi/lo inputs,
// cp.async double-buffered, pure LDS/ldmatrix + MMA mainloop.
// ===========================================================================
struct ABuf {
    uint32_t Kh[64 * LWW];
    uint32_t Kl[64 * LWW];
    uint32_t Vh[64 * LWW];
    uint32_t Vl[64 * LWW];
};                          // 36864 B
struct ASmem {
    uint32_t Qh[64 * LWW];
    uint32_t Ql[64 * LWW];
    ABuf buf[2];
};                          // 18432 + 73728 = 92160 B

// load one 64-row bf16x2-word tile array (512 x 16B segs) via cp.async
__device__ __forceinline__ void load_tile(uint32_t dstbase,
                                          const uint32_t* __restrict__ src,
                                          long rowbase, int tid) {
#pragma unroll
    for (int i = 0; i < 4; i++) {
        int idx = tid + i * 128;
        int r = idx >> 3, seg = idx & 7;
        cp16(dstbase + (uint32_t)(r * LWW + seg * 4) * 4,
             &src[(rowbase + r) * 32 + seg * 4]);
    }
}

__global__ __launch_bounds__(128) void attn_kernel()
{
    extern __shared__ char smraw2[];
    ASmem& sm = *reinterpret_cast<ASmem*>(smraw2);

    const int tid = threadIdx.x;
    const int warp = tid >> 5;
    const int lane = tid & 31;
    const int lr = lane >> 2;
    const int lc = (lane & 3) * 2;
    const int ql = lane & 3;
    const int bb = blockIdx.y;

    int rem = blockIdx.x;
    int tq = 0;
#pragma unroll 1
    for (; tq < 64; tq++) {
        int nt = min(tq + 2, 64);
        int nc = (nt + CHUNK - 1) >> 3;
        if (rem < nc) break;
        rem -= nc;
    }
    const int c = rem;
    const int q0 = tq * 64;
    const int ntiles = min(tq + 2, Tt / 64);
    const int tstart = c * CHUNK;
    const int tend = min(tstart + CHUNK, ntiles);

    const long brow = (long)bb * Tt;

    // prologue: Q hi/lo + first K/V tile
    {
        load_tile(smem_u32(sm.Qh), g_Qh, brow + q0, tid);
        load_tile(smem_u32(sm.Ql), g_Ql, brow + q0, tid);
        const long j0 = tstart * 64;
        load_tile(smem_u32(sm.buf[0].Kh), g_Kh, brow + j0, tid);
        load_tile(smem_u32(sm.buf[0].Kl), g_Kl, brow + j0, tid);
        load_tile(smem_u32(sm.buf[0].Vh), g_Vh, brow + j0, tid);
        load_tile(smem_u32(sm.buf[0].Vl), g_Vl, brow + j0, tid);
        CP_COMMIT();
    }

    float m0 = -3.0e38f, m1 = -3.0e38f, l0 = 0.f, l1 = 0.f;
    float oacc[8][4];
#pragma unroll
    for (int n = 0; n < 8; n++)
#pragma unroll
        for (int e = 0; e < 4; e++) oacc[n][e] = 0.f;

    const int qrow = warp * 16 + lr;
    // ldmatrix per-lane address offset into a V array:
    // matrix group g: rows (g&1)*8 + j (j = lane&7), col block (g>>1)*8
    const uint32_t vofs = (uint32_t)((((lane >> 3) & 1) * 8 + (lane & 7)) * 144 +
                                     ((lane >> 4) * 16));

    for (int t = tstart; t < tend; t++) {
        const int j0 = t * 64;
        const ABuf& cur = sm.buf[(t - tstart) & 1];
        CP_WAIT0();
        __syncthreads();

        if (t + 1 < tend) {
            const long j1 = (long)(t + 1) * 64;
            ABuf& nxt = sm.buf[(t + 1 - tstart) & 1];
            load_tile(smem_u32(nxt.Kh), g_Kh, brow + j1, tid);
            load_tile(smem_u32(nxt.Kl), g_Kl, brow + j1, tid);
            load_tile(smem_u32(nxt.Vh), g_Vh, brow + j1, tid);
            load_tile(smem_u32(nxt.Vl), g_Vl, brow + j1, tid);
            CP_COMMIT();
        }

        // ---- S = Q K^T (bf16x3, pure LDS fragments) ----
        float sc[8][4];
#pragma unroll
        for (int n = 0; n < 8; n++)
#pragma unroll
            for (int e = 0; e < 4; e++) sc[n][e] = 0.f;
#pragma unroll
        for (int s = 0; s < 4; s++) {
            const int qw = qrow * LWW + 8 * s + ql;
            uint32_t ah0 = sm.Qh[qw];
            uint32_t ah1 = sm.Qh[qw + 8 * LWW];
            uint32_t ah2 = sm.Qh[qw + 4];
            uint32_t ah3 = sm.Qh[qw + 8 * LWW + 4];
            uint32_t al0 = sm.Ql[qw];
            uint32_t al1 = sm.Ql[qw + 8 * LWW];
            uint32_t al2 = sm.Ql[qw + 4];
            uint32_t al3 = sm.Ql[qw + 8 * LWW + 4];
#pragma unroll
            for (int n = 0; n < 8; n++) {
                const int kw = (n * 8 + lr) * LWW + 8 * s + ql;
                uint32_t bh0 = cur.Kh[kw];
                uint32_t bh1 = cur.Kh[kw + 4];
                uint32_t bl0 = cur.Kl[kw];
                uint32_t bl1 = cur.Kl[kw + 4];
                mma_bf16(sc[n], ah0, ah1, ah2, ah3, bh0, bh1);
                mma_bf16(sc[n], ah0, ah1, ah2, ah3, bl0, bl1);
                mma_bf16(sc[n], al0, al1, al2, al3, bh0, bh1);
            }
        }

        // ---- causal mask (diag offset +1) ----
        if (j0 >= q0) {
            const int i0 = q0 + qrow;
#pragma unroll
            for (int n = 0; n < 8; n++) {
                int j = j0 + n * 8 + lc;
                if (j     > i0 + 1) sc[n][0] = -3.0e38f;
                if (j + 1 > i0 + 1) sc[n][1] = -3.0e38f;
                if (j     > i0 + 9) sc[n][2] = -3.0e38f;
                if (j + 1 > i0 + 9) sc[n][3] = -3.0e38f;
            }
        }

        // ---- register online softmax ----
        float rmax0 = -3.0e38f, rmax1 = -3.0e38f;
#pragma unroll
        for (int n = 0; n < 8; n++) {
            rmax0 = fmaxf(rmax0, fmaxf(sc[n][0], sc[n][1]));
            rmax1 = fmaxf(rmax1, fmaxf(sc[n][2], sc[n][3]));
        }
        rmax0 = fmaxf(rmax0, __shfl_xor_sync(0xffffffffu, rmax0, 1));
        rmax0 = fmaxf(rmax0, __shfl_xor_sync(0xffffffffu, rmax0, 2));
        rmax1 = fmaxf(rmax1, __shfl_xor_sync(0xffffffffu, rmax1, 1));
        rmax1 = fmaxf(rmax1, __shfl_xor_sync(0xffffffffu, rmax1, 2));
        float mn0 = fmaxf(m0, rmax0), mn1 = fmaxf(m1, rmax1);
        float alpha0 = exp2f((m0 - mn0) * S2L2E);
        float alpha1 = exp2f((m1 - mn1) * S2L2E);
        m0 = mn0; m1 = mn1;
        const float me0 = fmaxf(mn0, -1.0e30f);
        const float me1 = fmaxf(mn1, -1.0e30f);
        float ps0 = 0.f, ps1 = 0.f;
#pragma unroll
        for (int n = 0; n < 8; n++) {
            sc[n][0] = exp2f((sc[n][0] - me0) * S2L2E);
            sc[n][1] = exp2f((sc[n][1] - me0) * S2L2E);
            sc[n][2] = exp2f((sc[n][2] - me1) * S2L2E);
            sc[n][3] = exp2f((sc[n][3] - me1) * S2L2E);
            ps0 += sc[n][0] + sc[n][1];
            ps1 += sc[n][2] + sc[n][3];
        }
        ps0 += __shfl_xor_sync(0xffffffffu, ps0, 1);
        ps0 += __shfl_xor_sync(0xffffffffu, ps0, 2);
        ps1 += __shfl_xor_sync(0xffffffffu, ps1, 1);
        ps1 += __shfl_xor_sync(0xffffffffu, ps1, 2);
        l0 = l0 * alpha0 + ps0;
        l1 = l1 * alpha1 + ps1;
#pragma unroll
        for (int n = 0; n < 8; n++) {
            oacc[n][0] *= alpha0; oacc[n][1] *= alpha0;
            oacc[n][2] *= alpha1; oacc[n][3] *= alpha1;
        }

        // ---- O += P V (bf16x3); P in registers, V via ldmatrix.trans ----
        const uint32_t vhb = smem_u32(cur.Vh) + vofs;
        const uint32_t vlb = smem_u32(cur.Vl) + vofs;
#pragma unroll
        for (int s = 0; s < 4; s++) {
            const int t0 = 2 * s, t1 = 2 * s + 1;
            uint32_t ph0 = packbf(sc[t0][0], sc[t0][1]);
            uint32_t ph1 = packbf(sc[t0][2], sc[t0][3]);
            uint32_t ph2 = packbf(sc[t1][0], sc[t1][1]);
            uint32_t ph3 = packbf(sc[t1][2], sc[t1][3]);
            __nv_bfloat162* hp;
            uint32_t pl0, pl1, pl2, pl3;
            hp = (__nv_bfloat162*)&ph0;
            pl0 = packbf(sc[t0][0] - __bfloat162float(hp->x),
                         sc[t0][1] - __bfloat162float(hp->y));
            hp = (__nv_bfloat162*)&ph1;
            pl1 = packbf(sc[t0][2] - __bfloat162float(hp->x),
                         sc[t0][3] - __bfloat162float(hp->y));
            hp = (__nv_bfloat162*)&ph2;
            pl2 = packbf(sc[t1][0] - __bfloat162float(hp->x),
                         sc[t1][1] - __bfloat162float(hp->y));
            hp = (__nv_bfloat162*)&ph3;
            pl3 = packbf(sc[t1][2] - __bfloat162float(hp->x),
                         sc[t1][3] - __bfloat162float(hp->y));
            const uint32_t sb = (uint32_t)(s * 2304);   // 16 rows * 144B
#pragma unroll
            for (int np = 0; np < 4; np++) {
                uint32_t bh0, bh1, bh2, bh3, bl0, bl1, bl2, bl3;
                ldmatrix_x4_trans(bh0, bh1, bh2, bh3, vhb + sb + np * 32);
                ldmatrix_x4_trans(bl0, bl1, bl2, bl3, vlb + sb + np * 32);
                mma_bf16(oacc[2 * np],     ph0, ph1, ph2, ph3, bh0, bh1);
                mma_bf16(oacc[2 * np],     ph0, ph1, ph2, ph3, bl0, bl1);
                mma_bf16(oacc[2 * np],     pl0, pl1, pl2, pl3, bh0, bh1);
                mma_bf16(oacc[2 * np + 1], ph0, ph1, ph2, ph3, bh2, bh3);
                mma_bf16(oacc[2 * np + 1], ph0, ph1, ph2, ph3, bl2, bl3);
                mma_bf16(oacc[2 * np + 1], pl0, pl1, pl2, pl3, bh2, bh3);
            }
        }
        __syncthreads();
    }

    const long pbase = (((long)bb * 64 + tq) * MAXC + c) * 64;
    float* Op = g_Opart + pbase * 64;
#pragma unroll
    for (int n = 0; n < 8; n++) {
        int col = n * 8 + lc;
        *(float2*)&Op[(long)qrow * 64 + col] = make_float2(oacc[n][0], oacc[n][1]);
        *(float2*)&Op[(long)(qrow + 8) * 64 + col] = make_float2(oacc[n][2], oacc[n][3]);
    }
    if ((lane & 3) == 0) {
        g_Mpart[pbase + qrow] = m0;
        g_Mpart[pbase + qrow + 8] = m1;
        g_Lpart[pbase + qrow] = l0;
        g_Lpart[pbase + qrow + 8] = l1;
    }
}

// ===========================================================================
// Phase 2: merge partials (unchanged).
// ===========================================================================
__global__ __launch_bounds__(256) void merge_kernel(float* __restrict__ out)
{
    const int tid = threadIdx.x;
    const int r = tid >> 2;
    const int cg = (tid & 3) * 16;
    const int tq = blockIdx.x;
    const int bb = blockIdx.y;

    const int ntiles = min(tq + 2, Tt / 64);
    const int nc = (ntiles + CHUNK - 1) >> 3;
    const long base = ((long)bb * 64 + tq) * MAXC;

    float M = -3.0e38f;
    for (int c = 0; c < nc; c++)
        M = fmaxf(M, g_Mpart[(base + c) * 64 + r]);

    float acc[16];
#pragma unroll
    for (int i = 0; i < 16; i++) acc[i] = 0.f;
    float ltot = 0.f;

    for (int c = 0; c < nc; c++) {
        float mc = g_Mpart[(base + c) * 64 + r];
        float w = exp2f((mc - M) * S2L2E);
        ltot += w * g_Lpart[(base + c) * 64 + r];
        const float* Op = g_Opart + ((base + c) * 64 + r) * 64 + cg;
#pragma unroll
        for (int i = 0; i < 4; i++) {
            float4 v = *(const float4*)&Op[i * 4];
            acc[i * 4 + 0] += w * v.x;
            acc[i * 4 + 1] += w * v.y;
            acc[i * 4 + 2] += w * v.z;
            acc[i * 4 + 3] += w * v.w;
        }
    }

    const float inv = 1.0f / ltot;
    float* orow = out + ((long)bb * Tt + tq * 64 + r) * Hh + cg;
#pragma unroll
    for (int i = 0; i < 4; i++) {
        float4 o;
        o.x = acc[i * 4 + 0] * inv;
        o.y = acc[i * 4 + 1] * inv;
        o.z = acc[i * 4 + 2] * inv;
        o.w = acc[i * 4 + 3] * inv;
        *(float4*)&orow[i * 4] = o;
    }
}

// ===========================================================================
extern "C" void kernel_launch(void* const* d_in, const int* in_sizes, int n_in,
                              void* d_out, int out_size)
{
    const float* q  = (const float*)d_in[0];
    const float* k  = (const float*)d_in[1];
    const float* v  = (const float*)d_in[2];
    const float* Wq = (const float*)d_in[3];
    const float* Wk = (const float*)d_in[4];
    const float* Wv = (const float*)d_in[5];
    float* out = (float*)d_out;

    cudaFuncSetAttribute(proj_kernel,
                         cudaFuncAttributeMaxDynamicSharedMemorySize,
                         (int)(2 * sizeof(PBuf)));
    cudaFuncSetAttribute(attn_kernel,
                         cudaFuncAttributeMaxDynamicSharedMemorySize,
                         (int)sizeof(ASmem));

    dim3 pgrid((Bb * Tt) / 128, 1, 3);
    proj_kernel<<<pgrid, 128, 2 * sizeof(PBuf)>>>(q, k, v, Wq, Wk, Wv);
    attn_kernel<<<dim3(NCHUNKS, Bb), 128, sizeof(ASmem)>>>();
    merge_kernel<<<dim3(Tt / 64, Bb), 256>>>(out);
}